// round 12
// baseline (speedup 1.0000x reference)
#include <cuda_runtime.h>
#include <cuda_bf16.h>
#include <math.h>
#include <stdint.h>

#define VERY_NEG (-1e30f)

constexpr int Bz = 128;
constexpr int S  = 256;
constexpr int H  = 256;
constexpr int NH = 8;
constexpr int Dh = 32;
constexpr int C  = 20000;
constexpr int A  = 8;
constexpr int BS = Bz * S;
constexpr int CA = C * A;
constexpr int FF = 4 * H;
constexpr int NODES1 = 25001;
constexpr int QKVN = 3 * H;

// ---------------- scratch ------------------------------------------------------
__device__ uint32_t g_eh [(size_t)NODES1 * 128];
__device__ uint32_t g_el [(size_t)NODES1 * 128];
__device__ float    g_s  [CA];
__device__ float    g_dag[(size_t)C * H];
__device__ float    g_xv [(size_t)BS * H];
__device__ float    g_xd [(size_t)BS * H];
__device__ uint32_t g_xvh[(size_t)BS * 128], g_xvl[(size_t)BS * 128];
__device__ uint32_t g_xdh[(size_t)BS * 128], g_xdl[(size_t)BS * 128];
__device__ float    g_qkv[2][(size_t)BS * QKVN];
__device__ uint32_t g_cth[2][(size_t)BS * 128], g_ctl[2][(size_t)BS * 128];
__device__ float    g_t  [2][(size_t)BS * H];
__device__ uint32_t g_th [2][(size_t)BS * 128], g_tl [2][(size_t)BS * 128];
__device__ uint32_t g_fh [2][(size_t)BS * 512], g_fl [2][(size_t)BS * 512];
__device__ float    g_xdo[(size_t)BS * H];
__device__ uint32_t g_wqkvh[2][128 * QKVN], g_wqkvl[2][128 * QKVN];
__device__ uint32_t g_woh [2][128 * 256],  g_wol [2][128 * 256];
__device__ uint32_t g_f1h [2][128 * 1024], g_f1l [2][128 * 1024];
__device__ uint32_t g_f2h [2][512 * 256],  g_f2l [2][512 * 256];
__device__ uint32_t g_w1h [256 * 256],  g_w1l [256 * 256];

// ---------------- helpers ------------------------------------------------------
__device__ __forceinline__ void mma_bf16(float* c, const uint32_t* a, const uint32_t* b) {
    asm volatile(
        "mma.sync.aligned.m16n8k16.row.col.f32.bf16.bf16.f32 "
        "{%0,%1,%2,%3}, {%4,%5,%6,%7}, {%8,%9}, {%0,%1,%2,%3};\n"
        : "+f"(c[0]), "+f"(c[1]), "+f"(c[2]), "+f"(c[3])
        : "r"(a[0]), "r"(a[1]), "r"(a[2]), "r"(a[3]),
          "r"(b[0]), "r"(b[1]));
}

__device__ __forceinline__ void split2(float x0, float x1, uint32_t& hi, uint32_t& lo) {
    __nv_bfloat16 h0 = __float2bfloat16_rn(x0);
    __nv_bfloat16 h1 = __float2bfloat16_rn(x1);
    __nv_bfloat16 l0 = __float2bfloat16_rn(x0 - __bfloat162float(h0));
    __nv_bfloat16 l1 = __float2bfloat16_rn(x1 - __bfloat162float(h1));
    hi = ((uint32_t)__bfloat16_as_ushort(h1) << 16) | __bfloat16_as_ushort(h0);
    lo = ((uint32_t)__bfloat16_as_ushort(l1) << 16) | __bfloat16_as_ushort(l0);
}

__global__ void pack_contig_kernel(const float* __restrict__ src, uint32_t* __restrict__ dh,
                                   uint32_t* __restrict__ dl, int n2)
{
    int idx = blockIdx.x * blockDim.x + threadIdx.x;
    if (idx >= n2) return;
    float2 v = ((const float2*)src)[idx];
    uint32_t h, l;
    split2(v.x, v.y, h, l);
    dh[idx] = h; dl[idx] = l;
}

// merged weight pack: 13 segments in one launch
struct PackSeg {
    const float* src;
    uint32_t *dh, *dl;
    int Khalf, Nsrc, Ndst, coff, start;
};
struct PackAll { PackSeg seg[13]; int total; };

__global__ void pack_all_kernel(PackAll pa)
{
    int idx = blockIdx.x * blockDim.x + threadIdx.x;
    if (idx >= pa.total) return;
    int si = 0;
    #pragma unroll
    for (int i = 1; i < 13; i++)
        if (idx >= pa.seg[i].start) si = i;
    const PackSeg& sg = pa.seg[si];
    int li = idx - sg.start;
    int kp = li / sg.Nsrc, n = li - kp * sg.Nsrc;
    float a = sg.src[(size_t)(2 * kp) * sg.Nsrc + n];
    float b = sg.src[(size_t)(2 * kp + 1) * sg.Nsrc + n];
    uint32_t h, l;
    split2(a, b, h, l);
    sg.dh[(size_t)kp * sg.Ndst + sg.coff + n] = h;
    sg.dl[(size_t)kp * sg.Ndst + sg.coff + n] = l;
}

__global__ void s_init_kernel(float* __restrict__ s, const float* __restrict__ b2)
{
    int idx = blockIdx.x * blockDim.x + threadIdx.x;
    if (idx < CA) s[idx] = b2[0];
}

// ---------------- pointer-pair arg block (z selects encoder) -------------------
struct G2 {
    const uint32_t *Ah0, *Al0, *Bh0, *Bl0;
    const uint32_t *Ah1, *Al1, *Bh1, *Bl1;
    const float *bias0, *bias1, *Res0, *Res1;
    float *Cm0, *Cm1;
    uint32_t *Ch0, *Cl0, *Ch1, *Cl1;
};

// ---------------- split-bf16 tensor GEMM: 128x64 CTA tile, 3 CTAs/SM ----------
template <bool RELU, bool BIAS, bool RES, bool GATHER, bool OUTF32, bool SPLIT, bool SCORE>
__global__ __launch_bounds__(256, 3)
void tgemm_kernel(G2 g, const float* __restrict__ w2, float* __restrict__ sout,
                  int M, int N, int K,
                  const int* __restrict__ gl, const int* __restrict__ ga)
{
    // A stride 12 -> conflict-free fragment LDS; B tile 8 kpairs x 64 cols pad 72
    __shared__ uint32_t As_h[2][128][12];
    __shared__ uint32_t As_l[2][128][12];
    __shared__ uint32_t Bs_h[2][8][72];
    __shared__ uint32_t Bs_l[2][8][72];

    const int z = blockIdx.z;
    const uint32_t* __restrict__ Ah = z ? g.Ah1 : g.Ah0;
    const uint32_t* __restrict__ Al = z ? g.Al1 : g.Al0;
    const uint32_t* __restrict__ Bh = z ? g.Bh1 : g.Bh0;
    const uint32_t* __restrict__ Bl = z ? g.Bl1 : g.Bl0;
    const float* __restrict__ bias  = z ? g.bias1 : g.bias0;
    const float* __restrict__ Res   = z ? g.Res1 : g.Res0;
    float* __restrict__ Cm          = z ? g.Cm1 : g.Cm0;
    uint32_t* __restrict__ Ch       = z ? g.Ch1 : g.Ch0;
    uint32_t* __restrict__ Cl       = z ? g.Cl1 : g.Cl0;

    const int tid  = threadIdx.x;
    const int lane = tid & 31;
    const int wid  = tid >> 5;
    const int warp_m = wid & 3;        // 4 x 32 rows
    const int warp_n = wid >> 2;       // 2 x 32 cols
    const int m0 = blockIdx.y * 128, n0 = blockIdx.x * 64;
    const int r = lane >> 2, c = lane & 3;
    const int Khalf = K >> 1;

    int arow[2], akp2[2];
    #pragma unroll
    for (int i = 0; i < 2; i++) {
        int idx = tid + i * 256;
        arow[i] = idx >> 2;  akp2[i] = (idx & 3) << 1;
    }
    const int bkp = tid >> 5;               // 0..7
    const int bcol2 = (tid & 31) << 1;      // 0..62

    int grow_l[2], grow_a[2];
    if (GATHER) {
        #pragma unroll
        for (int i = 0; i < 2; i++) {
            grow_l[i] = gl[m0 + arow[i]];
            grow_a[i] = ga[m0 + arow[i]];
        }
    }

    float acc[2][4][4] = {};
    uint2 pah[2], pal[2], pbh, pbl;

    auto load_tile = [&](int k0) {
        const int kpb = k0 >> 1;
        #pragma unroll
        for (int i = 0; i < 2; i++) {
            size_t aaddr;
            if (GATHER) {
                const int kglob = k0 + akp2[i] * 2;
                const int src = (kglob < 256) ? grow_l[i] : grow_a[i];
                aaddr = (size_t)src * 128 + ((kpb + akp2[i]) & 127);
            } else {
                aaddr = (size_t)(m0 + arow[i]) * Khalf + kpb + akp2[i];
            }
            pah[i] = *(const uint2*)&Ah[aaddr];
            pal[i] = *(const uint2*)&Al[aaddr];
        }
        const size_t ba = (size_t)(kpb + bkp) * N + n0 + bcol2;
        pbh = *(const uint2*)&Bh[ba];
        pbl = *(const uint2*)&Bl[ba];
    };

    auto store_tile = [&](int buf) {
        #pragma unroll
        for (int i = 0; i < 2; i++) {
            *(uint2*)&As_h[buf][arow[i]][akp2[i]] = pah[i];
            *(uint2*)&As_l[buf][arow[i]][akp2[i]] = pal[i];
        }
        *(uint2*)&Bs_h[buf][bkp][bcol2] = pbh;
        *(uint2*)&Bs_l[buf][bkp][bcol2] = pbl;
    };

    load_tile(0);
    store_tile(0);
    __syncthreads();

    const int ntiles = K >> 4;
    for (int t = 0; t < ntiles; t++) {
        const int cur = t & 1;
        if (t + 1 < ntiles) load_tile((t + 1) << 4);

        uint32_t a_h[2][4], a_l[2][4], b_h[4][2], b_l[4][2];
        #pragma unroll
        for (int mt = 0; mt < 2; mt++) {
            const int row = warp_m * 32 + mt * 16 + r;
            a_h[mt][0] = As_h[cur][row][c];
            a_h[mt][1] = As_h[cur][row + 8][c];
            a_h[mt][2] = As_h[cur][row][c + 4];
            a_h[mt][3] = As_h[cur][row + 8][c + 4];
            a_l[mt][0] = As_l[cur][row][c];
            a_l[mt][1] = As_l[cur][row + 8][c];
            a_l[mt][2] = As_l[cur][row][c + 4];
            a_l[mt][3] = As_l[cur][row + 8][c + 4];
        }
        #pragma unroll
        for (int nt = 0; nt < 4; nt++) {
            const int col = warp_n * 32 + nt * 8 + r;
            b_h[nt][0] = Bs_h[cur][c][col];
            b_h[nt][1] = Bs_h[cur][c + 4][col];
            b_l[nt][0] = Bs_l[cur][c][col];
            b_l[nt][1] = Bs_l[cur][c + 4][col];
        }

        #pragma unroll
        for (int mt = 0; mt < 2; mt++)
            #pragma unroll
            for (int nt = 0; nt < 4; nt++) {
                mma_bf16(acc[mt][nt], a_h[mt], b_h[nt]);
                mma_bf16(acc[mt][nt], a_h[mt], b_l[nt]);
                mma_bf16(acc[mt][nt], a_l[mt], b_h[nt]);
            }

        if (t + 1 < ntiles) {
            store_tile(cur ^ 1);
            __syncthreads();
        }
    }

    float partial[4] = {0.f, 0.f, 0.f, 0.f};

    #pragma unroll
    for (int mt = 0; mt < 2; mt++) {
        #pragma unroll
        for (int nt = 0; nt < 4; nt++) {
            const int row0 = m0 + warp_m * 32 + mt * 16 + r;
            const int col  = n0 + warp_n * 32 + nt * 8 + 2 * c;
            #pragma unroll
            for (int h = 0; h < 2; h++) {
                float2 v = make_float2(acc[mt][nt][h * 2], acc[mt][nt][h * 2 + 1]);
                if (BIAS) {
                    const float2 bb = *(const float2*)&bias[col];
                    v.x += bb.x; v.y += bb.y;
                }
                if (RELU) { v.x = fmaxf(v.x, 0.f); v.y = fmaxf(v.y, 0.f); }
                const int row = row0 + h * 8;
                const size_t off = (size_t)row * N + col;
                if (RES) {
                    const float2 rr = *(const float2*)&Res[off];
                    v.x += rr.x; v.y += rr.y;
                }
                if (SCORE) {
                    const float2 ww = *(const float2*)&w2[col];
                    partial[mt * 2 + h] += v.x * ww.x + v.y * ww.y;
                }
                if (OUTF32) *(float2*)&Cm[off] = v;
                if (SPLIT) {
                    uint32_t hw, lw;
                    split2(v.x, v.y, hw, lw);
                    Ch[(size_t)row * (N >> 1) + (col >> 1)] = hw;
                    Cl[(size_t)row * (N >> 1) + (col >> 1)] = lw;
                }
            }
        }
    }

    if (SCORE) {
        #pragma unroll
        for (int mt = 0; mt < 2; mt++)
            #pragma unroll
            for (int h = 0; h < 2; h++) {
                float p = partial[mt * 2 + h];
                p += __shfl_xor_sync(0xffffffffu, p, 1);
                p += __shfl_xor_sync(0xffffffffu, p, 2);
                if ((lane & 3) == 0) {
                    const int row = m0 + warp_m * 32 + mt * 16 + r + h * 8;
                    atomicAdd(&sout[row], p);
                }
            }
    }
}

// ---------------- DAG softmax + weighted ancestor sum --------------------------
__global__ void dag_softmax_kernel(const float* __restrict__ s, const float* __restrict__ mask,
                                   const int* __restrict__ anc, const float* __restrict__ emb,
                                   float* __restrict__ dag)
{
    int gw = (blockIdx.x * blockDim.x + threadIdx.x) >> 5;
    int lane = threadIdx.x & 31;
    if (gw >= C) return;
    float sv = -3.0e38f;
    int av = 0;
    if (lane < 8) {
        float m = mask[gw * 8 + lane];
        sv = s[gw * 8 + lane] + (1.f - m) * VERY_NEG;
        av = anc[gw * 8 + lane];
    }
    float mx = sv;
    #pragma unroll
    for (int off = 4; off; off >>= 1) mx = fmaxf(mx, __shfl_xor_sync(0xffffffffu, mx, off));
    float e = (lane < 8) ? __expf(sv - mx) : 0.f;
    float su = e;
    #pragma unroll
    for (int off = 4; off; off >>= 1) su += __shfl_xor_sync(0xffffffffu, su, off);
    float wv = e / su;
    float w8[8];
    int   a8[8];
    #pragma unroll
    for (int a = 0; a < 8; a++) {
        w8[a] = __shfl_sync(0xffffffffu, wv, a);
        a8[a] = __shfl_sync(0xffffffffu, av, a);
    }
    const float4* e4 = (const float4*)emb;
    #pragma unroll
    for (int rep = 0; rep < 2; rep++) {
        int f4i = lane + rep * 32;
        float4 acc = make_float4(0.f, 0.f, 0.f, 0.f);
        #pragma unroll
        for (int a = 0; a < 8; a++) {
            float4 v = e4[(size_t)a8[a] * 64 + f4i];
            acc.x = fmaf(w8[a], v.x, acc.x);
            acc.y = fmaf(w8[a], v.y, acc.y);
            acc.z = fmaf(w8[a], v.z, acc.z);
            acc.w = fmaf(w8[a], v.w, acc.w);
        }
        ((float4*)dag)[(size_t)gw * 64 + f4i] = acc;
    }
}

__global__ void embed_gather_kernel(const int* __restrict__ ids, const float* __restrict__ embw,
                                    const float* __restrict__ dag,
                                    float* __restrict__ xv, float* __restrict__ xd,
                                    uint32_t* __restrict__ xvh, uint32_t* __restrict__ xvl,
                                    uint32_t* __restrict__ xdh, uint32_t* __restrict__ xdl)
{
    int idx = blockIdx.x * blockDim.x + threadIdx.x;
    if (idx >= BS * 64) return;
    int bs = idx >> 6, h4 = idx & 63;
    int id = ids[bs];
    float4 vv = ((const float4*)embw)[(size_t)id * 64 + h4];
    ((float4*)xv)[(size_t)bs * 64 + h4] = vv;
    float4 dv = make_float4(0.f, 0.f, 0.f, 0.f);
    if (id > 0) dv = ((const float4*)dag)[(size_t)(id - 1) * 64 + h4];
    ((float4*)xd)[(size_t)bs * 64 + h4] = dv;

    uint32_t h0, l0, h1, l1;
    split2(vv.x, vv.y, h0, l0);
    split2(vv.z, vv.w, h1, l1);
    xvh[(size_t)bs * 128 + h4 * 2]     = h0;
    xvh[(size_t)bs * 128 + h4 * 2 + 1] = h1;
    xvl[(size_t)bs * 128 + h4 * 2]     = l0;
    xvl[(size_t)bs * 128 + h4 * 2 + 1] = l1;
    split2(dv.x, dv.y, h0, l0);
    split2(dv.z, dv.w, h1, l1);
    xdh[(size_t)bs * 128 + h4 * 2]     = h0;
    xdh[(size_t)bs * 128 + h4 * 2 + 1] = h1;
    xdl[(size_t)bs * 128 + h4 * 2]     = l0;
    xdl[(size_t)bs * 128 + h4 * 2 + 1] = l1;
}

// ---------------- attention: SIMT chunked online softmax (z selects) ----------
struct A2 {
    const float *qkv0, *qkv1;
    uint32_t *h0, *l0, *h1, *l1;
};

__global__ void attention_kernel(A2 g, const float* __restrict__ cmask)
{
    extern __shared__ float sm[];
    float* Ks = sm;
    float* Vs = sm + S * Dh;
    float* madd = Vs + S * Dh;
    const int h = blockIdx.x, b = blockIdx.y, z = blockIdx.z;
    const float* __restrict__ QKV = z ? g.qkv1 : g.qkv0;
    uint32_t* __restrict__ cth = z ? g.h1 : g.h0;
    uint32_t* __restrict__ ctl = z ? g.l1 : g.l0;
    const int tid = threadIdx.x;
    const size_t rowbase = (size_t)b * S * QKVN;
    const int qo = h * Dh, ko = H + h * Dh, vo = 2 * H + h * Dh;

    for (int i = tid; i < S * 8; i += 256) {
        int row = i >> 3, slot = (i & 7) << 2;
        *(float4*)&Ks[row * Dh + slot] = *(const float4*)&QKV[rowbase + (size_t)row * QKVN + ko + slot];
        *(float4*)&Vs[row * Dh + slot] = *(const float4*)&QKV[rowbase + (size_t)row * QKVN + vo + slot];
    }
    madd[tid] = (1.0f - cmask[b * S + tid]) * VERY_NEG;
    __syncthreads();

    float q[32];
    const float* qp = &QKV[rowbase + (size_t)tid * QKVN + qo];
    #pragma unroll
    for (int i = 0; i < 32; i += 4) {
        float4 t = *(const float4*)&qp[i];
        q[i] = t.x; q[i + 1] = t.y; q[i + 2] = t.z; q[i + 3] = t.w;
    }
    const float scale = rsqrtf(32.0f);
    float m = -INFINITY, l = 0.f, o[32];
    #pragma unroll
    for (int i = 0; i < 32; i++) o[i] = 0.f;

    for (int k0 = 0; k0 < S; k0 += 16) {
        float sc[16];
        float cm = -INFINITY;
        #pragma unroll
        for (int kk = 0; kk < 16; kk++) {
            const float* kr = &Ks[(k0 + kk) * Dh];
            float d = 0.f;
            #pragma unroll
            for (int i = 0; i < 32; i++) d = fmaf(q[i], kr[i], d);
            sc[kk] = d * scale + madd[k0 + kk];
            cm = fmaxf(cm, sc[kk]);
        }
        const float mn = fmaxf(m, cm);
        const float corr = __expf(m - mn);
        l *= corr;
        #pragma unroll
        for (int i = 0; i < 32; i++) o[i] *= corr;
        #pragma unroll
        for (int kk = 0; kk < 16; kk++) {
            const float p = __expf(sc[kk] - mn);
            l += p;
            const float* vr = &Vs[(k0 + kk) * Dh];
            #pragma unroll
            for (int i = 0; i < 32; i++) o[i] = fmaf(p, vr[i], o[i]);
        }
        m = mn;
    }
    const float inv = 1.0f / l;
    const size_t prow = (size_t)(b * S + tid) * 128 + h * 16;
    #pragma unroll
    for (int i = 0; i < 32; i += 2) {
        uint32_t hw, lw;
        split2(o[i] * inv, o[i + 1] * inv, hw, lw);
        cth[prow + i / 2] = hw;
        ctl[prow + i / 2] = lw;
    }
}

// ---------------- pooling ------------------------------------------------------
__global__ void pool_kernel(const float* __restrict__ x, const float* __restrict__ cmask,
                            const float* __restrict__ pw, const float* __restrict__ pb,
                            float* __restrict__ out)
{
    __shared__ float spw[H];
    __shared__ float sc[S];
    __shared__ float red[8];
    const int b = blockIdx.x, tid = threadIdx.x;
    const int lane = tid & 31, w = tid >> 5;
    spw[tid] = pw[tid];
    __syncthreads();

    for (int row = w; row < S; row += 8) {
        const float* xp = &x[((size_t)b * S + row) * H];
        float4 a0 = *(const float4*)&xp[lane * 4];
        float4 a1 = *(const float4*)&xp[128 + lane * 4];
        float acc = a0.x * spw[lane * 4 + 0] + a0.y * spw[lane * 4 + 1]
                  + a0.z * spw[lane * 4 + 2] + a0.w * spw[lane * 4 + 3]
                  + a1.x * spw[128 + lane * 4 + 0] + a1.y * spw[128 + lane * 4 + 1]
                  + a1.z * spw[128 + lane * 4 + 2] + a1.w * spw[128 + lane * 4 + 3];
        #pragma unroll
        for (int off = 16; off; off >>= 1) acc += __shfl_xor_sync(0xffffffffu, acc, off);
        if (lane == 0)
            sc[row] = acc + pb[0] + (1.f - cmask[b * S + row]) * VERY_NEG;
    }
    __syncthreads();

    float v = sc[tid];
    float mx = v;
    #pragma unroll
    for (int off = 16; off; off >>= 1) mx = fmaxf(mx, __shfl_xor_sync(0xffffffffu, mx, off));
    if (lane == 0) red[w] = mx;
    __syncthreads();
    float bm = red[0];
    #pragma unroll
    for (int i = 1; i < 8; i++) bm = fmaxf(bm, red[i]);
    __syncthreads();
    float e = __expf(v - bm);
    float su = e;
    #pragma unroll
    for (int off = 16; off; off >>= 1) su += __shfl_xor_sync(0xffffffffu, su, off);
    if (lane == 0) red[w] = su;
    __syncthreads();
    float tot = 0.f;
    #pragma unroll
    for (int i = 0; i < 8; i++) tot += red[i];
    sc[tid] = e / tot;
    __syncthreads();

    float acc = 0.f;
    for (int ss = 0; ss < S; ss++)
        acc = fmaf(sc[ss], x[((size_t)b * S + ss) * H + tid], acc);
    out[(size_t)b * H + tid] = acc;
}

// ---------------- host ----------------------------------------------------------
extern "C" void kernel_launch(void* const* d_in, const int* in_sizes, int n_in,
                              void* d_out, int out_size)
{
    const int*   input_ids   = (const int*)d_in[0];
    const float* code_mask   = (const float*)d_in[1];
    const int*   dx_leaves   = (const int*)d_in[2];
    const int*   dx_anc      = (const int*)d_in[3];
    const float* dx_mask     = (const float*)d_in[4];
    const float* embed_init  = (const float*)d_in[5];
    const float* embed_inp   = (const float*)d_in[6];
    const float* attn_w1     = (const float*)d_in[7];
    const float* attn_b1     = (const float*)d_in[8];
    const float* attn_w2     = (const float*)d_in[9];
    const float* attn_b2     = (const float*)d_in[10];
    const float* pool_w      = (const float*)d_in[11];
    const float* pool_b      = (const float*)d_in[12];
    const float* enc_w[2][8];
    for (int z = 0; z < 2; z++)
        for (int j = 0; j < 8; j++)
            enc_w[z][j] = (const float*)d_in[13 + z * 8 + j];
    float* out = (float*)d_out;

    uint32_t *eh, *el, *xvh, *xvl, *xdh, *xdl, *w1h, *w1l;
    uint32_t *cth[2], *ctl[2], *th[2], *tl[2], *fh[2], *fl[2];
    uint32_t *wqkvh[2], *wqkvl[2], *woh[2], *wol[2], *f1h[2], *f1l[2], *f2h[2], *f2l[2];
    float *s, *dag, *xv, *xd, *xdo, *qkv[2], *t[2];
    {
        char* p;
        cudaGetSymbolAddress((void**)&eh, g_eh);   cudaGetSymbolAddress((void**)&el, g_el);
        cudaGetSymbolAddress((void**)&s, g_s);     cudaGetSymbolAddress((void**)&dag, g_dag);
        cudaGetSymbolAddress((void**)&xv, g_xv);   cudaGetSymbolAddress((void**)&xd, g_xd);
        cudaGetSymbolAddress((void**)&xvh, g_xvh); cudaGetSymbolAddress((void**)&xvl, g_xvl);
        cudaGetSymbolAddress((void**)&xdh, g_xdh); cudaGetSymbolAddress((void**)&xdl, g_xdl);
        cudaGetSymbolAddress((void**)&xdo, g_xdo);
        cudaGetSymbolAddress((void**)&w1h, g_w1h); cudaGetSymbolAddress((void**)&w1l, g_w1l);
        cudaGetSymbolAddress((void**)&p, g_qkv);   qkv[0] = (float*)p;    qkv[1] = qkv[0] + (size_t)BS * QKVN;
        cudaGetSymbolAddress((void**)&p, g_t);     t[0] = (float*)p;      t[1] = t[0] + (size_t)BS * H;
        cudaGetSymbolAddress((void**)&p, g_cth);   cth[0] = (uint32_t*)p; cth[1] = cth[0] + (size_t)BS * 128;
        cudaGetSymbolAddress((void**)&p, g_ctl);   ctl[0] = (uint32_t*)p; ctl[1] = ctl[0] + (size_t)BS * 128;
        cudaGetSymbolAddress((void**)&p, g_th);    th[0] = (uint32_t*)p;  th[1] = th[0] + (size_t)BS * 128;
        cudaGetSymbolAddress((void**)&p, g_tl);    tl[0] = (uint32_t*)p;  tl[1] = tl[0] + (size_t)BS * 128;
        cudaGetSymbolAddress((void**)&p, g_fh);    fh[0] = (uint32_t*)p;  fh[1] = fh[0] + (size_t)BS * 512;
        cudaGetSymbolAddress((void**)&p, g_fl);    fl[0] = (uint32_t*)p;  fl[1] = fl[0] + (size_t)BS * 512;
        cudaGetSymbolAddress((void**)&p, g_wqkvh); wqkvh[0] = (uint32_t*)p; wqkvh[1] = wqkvh[0] + 128 * QKVN;
        cudaGetSymbolAddress((void**)&p, g_wqkvl); wqkvl[0] = (uint32_t*)p; wqkvl[1] = wqkvl[0] + 128 * QKVN;
        cudaGetSymbolAddress((void**)&p, g_woh);   woh[0] = (uint32_t*)p;   woh[1] = woh[0] + 128 * 256;
        cudaGetSymbolAddress((void**)&p, g_wol);   wol[0] = (uint32_t*)p;   wol[1] = wol[0] + 128 * 256;
        cudaGetSymbolAddress((void**)&p, g_f1h);   f1h[0] = (uint32_t*)p;   f1h[1] = f1h[0] + 128 * 1024;
        cudaGetSymbolAddress((void**)&p, g_f1l);   f1l[0] = (uint32_t*)p;   f1l[1] = f1l[0] + 128 * 1024;
        cudaGetSymbolAddress((void**)&p, g_f2h);   f2h[0] = (uint32_t*)p;   f2h[1] = f2h[0] + 512 * 256;
        cudaGetSymbolAddress((void**)&p, g_f2l);   f2l[0] = (uint32_t*)p;   f2l[1] = f2l[0] + 512 * 256;
    }

    const int asmem = (2 * S * Dh + S) * (int)sizeof(float);
    cudaFuncSetAttribute(attention_kernel, cudaFuncAttributeMaxDynamicSharedMemorySize, asmem);

    const int PT = 256;
    pack_contig_kernel<<<(NODES1 * 128 + PT - 1) / PT, PT>>>(embed_init, eh, el, NODES1 * 128);
    s_init_kernel<<<(CA + PT - 1) / PT, PT>>>(s, attn_b2);

    // merged weight packing: 13 segments, one launch
    {
        PackAll pa{};
        int cur = 0, si = 0;
        auto add = [&](const float* src, uint32_t* dh, uint32_t* dl,
                       int Khalf, int Nsrc, int Ndst, int coff) {
            pa.seg[si] = {src, dh, dl, Khalf, Nsrc, Ndst, coff, cur};
            cur += Khalf * Nsrc;
            si++;
        };
        add(attn_w1, w1h, w1l, 256, 256, 256, 0);
        for (int z = 0; z < 2; z++) {
            add(enc_w[z][0], wqkvh[z], wqkvl[z], 128, 256, QKVN, 0);
            add(enc_w[z][1], wqkvh[z], wqkvl[z], 128, 256, QKVN, 256);
            add(enc_w[z][2], wqkvh[z], wqkvl[z], 128, 256, QKVN, 512);
            add(enc_w[z][3], woh[z], wol[z], 128, 256, 256, 0);
            add(enc_w[z][4], f1h[z], f1l[z], 128, 1024, 1024, 0);
            add(enc_w[z][6], f2h[z], f2l[z], 512, 256, 256, 0);
        }
        pa.total = cur;
        pack_all_kernel<<<(cur + PT - 1) / PT, PT>>>(pa);
    }

    // DAG MLP: gathered A + fused score (N=256 -> grid.x=4)
    {
        G2 g{};
        g.Ah0 = g.Ah1 = eh;  g.Al0 = g.Al1 = el;
        g.Bh0 = g.Bh1 = w1h; g.Bl0 = g.Bl1 = w1l;
        g.bias0 = g.bias1 = attn_b1;
        tgemm_kernel<true, true, false, true, false, false, true><<<dim3(4, CA / 128, 1), 256>>>(
            g, attn_w2, s, CA, 256, 512, dx_leaves, dx_anc);
    }
    dag_softmax_kernel<<<C / 8, 256>>>(s, dx_mask, dx_anc, embed_init, dag);
    embed_gather_kernel<<<(BS * 64 + PT - 1) / PT, PT>>>(input_ids, embed_inp, dag,
                                                         xv, xd, xvh, xvl, xdh, xdl);

    // --- both encoders batched over gridDim.z ---
    {
        G2 g{};
        g.Ah0 = xvh; g.Al0 = xvl; g.Ah1 = xdh; g.Al1 = xdl;
        g.Bh0 = wqkvh[0]; g.Bl0 = wqkvl[0]; g.Bh1 = wqkvh[1]; g.Bl1 = wqkvl[1];
        g.Cm0 = qkv[0]; g.Cm1 = qkv[1];
        tgemm_kernel<false, false, false, false, true, false, false><<<dim3(QKVN / 64, BS / 128, 2), 256>>>(
            g, nullptr, nullptr, BS, QKVN, H, nullptr, nullptr);
    }
    {
        A2 a{qkv[0], qkv[1], cth[0], ctl[0], cth[1], ctl[1]};
        attention_kernel<<<dim3(NH, Bz, 2), 256, asmem>>>(a, code_mask);
    }
    {
        G2 g{};
        g.Ah0 = cth[0]; g.Al0 = ctl[0]; g.Ah1 = cth[1]; g.Al1 = ctl[1];
        g.Bh0 = woh[0]; g.Bl0 = wol[0]; g.Bh1 = woh[1]; g.Bl1 = wol[1];
        g.Res0 = xv; g.Res1 = xd;
        g.Cm0 = t[0]; g.Cm1 = t[1];
        g.Ch0 = th[0]; g.Cl0 = tl[0]; g.Ch1 = th[1]; g.Cl1 = tl[1];
        tgemm_kernel<false, false, true, false, true, true, false><<<dim3(4, BS / 128, 2), 256>>>(
            g, nullptr, nullptr, BS, H, H, nullptr, nullptr);
    }
    {
        G2 g{};
        g.Ah0 = th[0]; g.Al0 = tl[0]; g.Ah1 = th[1]; g.Al1 = tl[1];
        g.Bh0 = f1h[0]; g.Bl0 = f1l[0]; g.Bh1 = f1h[1]; g.Bl1 = f1l[1];
        g.bias0 = enc_w[0][5]; g.bias1 = enc_w[1][5];
        g.Ch0 = fh[0]; g.Cl0 = fl[0]; g.Ch1 = fh[1]; g.Cl1 = fl[1];
        tgemm_kernel<true, true, false, false, false, true, false><<<dim3(FF / 64, BS / 128, 2), 256>>>(
            g, nullptr, nullptr, BS, FF, H, nullptr, nullptr);
    }
    {
        G2 g{};
        g.Ah0 = fh[0]; g.Al0 = fl[0]; g.Ah1 = fh[1]; g.Al1 = fl[1];
        g.Bh0 = f2h[0]; g.Bl0 = f2l[0]; g.Bh1 = f2h[1]; g.Bl1 = f2l[1];
        g.bias0 = enc_w[0][7]; g.bias1 = enc_w[1][7];
        g.Res0 = t[0]; g.Res1 = t[1];
        g.Cm0 = out; g.Cm1 = xdo;
        tgemm_kernel<false, true, true, false, true, false, false><<<dim3(4, BS / 128, 2), 256>>>(
            g, nullptr, nullptr, BS, H, FF, nullptr, nullptr);
    }

    pool_kernel<<<Bz, 256>>>(xdo, code_mask, pool_w, pool_b, out + (size_t)BS * H);
}

// round 13
// speedup vs baseline: 1.1928x; 1.1928x over previous
#include <cuda_runtime.h>
#include <cuda_bf16.h>
#include <math.h>
#include <stdint.h>

#define VERY_NEG (-1e30f)

constexpr int Bz = 128;
constexpr int S  = 256;
constexpr int H  = 256;
constexpr int NH = 8;
constexpr int Dh = 32;
constexpr int C  = 20000;
constexpr int A  = 8;
constexpr int BS = Bz * S;
constexpr int CA = C * A;
constexpr int FF = 4 * H;
constexpr int NODES1 = 25001;
constexpr int QKVN = 3 * H;

// ---------------- scratch ------------------------------------------------------
__device__ uint32_t g_eh [(size_t)NODES1 * 128];
__device__ uint32_t g_el [(size_t)NODES1 * 128];
__device__ float    g_s  [CA];
__device__ float    g_dag[(size_t)C * H];
__device__ float    g_xv [(size_t)BS * H];
__device__ float    g_xd [(size_t)BS * H];
__device__ uint32_t g_xvh[(size_t)BS * 128], g_xvl[(size_t)BS * 128];
__device__ uint32_t g_xdh[(size_t)BS * 128], g_xdl[(size_t)BS * 128];
__device__ float    g_qkv[2][(size_t)BS * QKVN];
__device__ uint32_t g_cth[2][(size_t)BS * 128], g_ctl[2][(size_t)BS * 128];
__device__ float    g_t  [2][(size_t)BS * H];
__device__ uint32_t g_th [2][(size_t)BS * 128], g_tl [2][(size_t)BS * 128];
__device__ uint32_t g_fh [2][(size_t)BS * 512], g_fl [2][(size_t)BS * 512];
__device__ float    g_xdo[(size_t)BS * H];
__device__ uint32_t g_wqkvh[2][128 * QKVN], g_wqkvl[2][128 * QKVN];
__device__ uint32_t g_woh [2][128 * 256],  g_wol [2][128 * 256];
__device__ uint32_t g_f1h [2][128 * 1024], g_f1l [2][128 * 1024];
__device__ uint32_t g_f2h [2][512 * 256],  g_f2l [2][512 * 256];
__device__ uint32_t g_w1h [256 * 256],  g_w1l [256 * 256];

// ---------------- helpers ------------------------------------------------------
__device__ __forceinline__ void mma_bf16(float* c, const uint32_t* a, const uint32_t* b) {
    asm volatile(
        "mma.sync.aligned.m16n8k16.row.col.f32.bf16.bf16.f32 "
        "{%0,%1,%2,%3}, {%4,%5,%6,%7}, {%8,%9}, {%0,%1,%2,%3};\n"
        : "+f"(c[0]), "+f"(c[1]), "+f"(c[2]), "+f"(c[3])
        : "r"(a[0]), "r"(a[1]), "r"(a[2]), "r"(a[3]),
          "r"(b[0]), "r"(b[1]));
}

__device__ __forceinline__ void split2(float x0, float x1, uint32_t& hi, uint32_t& lo) {
    __nv_bfloat16 h0 = __float2bfloat16_rn(x0);
    __nv_bfloat16 h1 = __float2bfloat16_rn(x1);
    __nv_bfloat16 l0 = __float2bfloat16_rn(x0 - __bfloat162float(h0));
    __nv_bfloat16 l1 = __float2bfloat16_rn(x1 - __bfloat162float(h1));
    hi = ((uint32_t)__bfloat16_as_ushort(h1) << 16) | __bfloat16_as_ushort(h0);
    lo = ((uint32_t)__bfloat16_as_ushort(l1) << 16) | __bfloat16_as_ushort(l0);
}

#define CP_ASYNC8(dst, src) \
    asm volatile("cp.async.ca.shared.global [%0], [%1], 8;" :: "r"(dst), "l"(src) : "memory")
#define CP_COMMIT()  asm volatile("cp.async.commit_group;" ::: "memory")
#define CP_WAIT0()   asm volatile("cp.async.wait_group 0;" ::: "memory")

__global__ void pack_contig_kernel(const float* __restrict__ src, uint32_t* __restrict__ dh,
                                   uint32_t* __restrict__ dl, int n2)
{
    int idx = blockIdx.x * blockDim.x + threadIdx.x;
    if (idx >= n2) return;
    float2 v = ((const float2*)src)[idx];
    uint32_t h, l;
    split2(v.x, v.y, h, l);
    dh[idx] = h; dl[idx] = l;
}

// merged weight pack: 13 segments in one launch
struct PackSeg {
    const float* src;
    uint32_t *dh, *dl;
    int Khalf, Nsrc, Ndst, coff, start;
};
struct PackAll { PackSeg seg[13]; int total; };

__global__ void pack_all_kernel(PackAll pa)
{
    int idx = blockIdx.x * blockDim.x + threadIdx.x;
    if (idx >= pa.total) return;
    int si = 0;
    #pragma unroll
    for (int i = 1; i < 13; i++)
        if (idx >= pa.seg[i].start) si = i;
    const PackSeg& sg = pa.seg[si];
    int li = idx - sg.start;
    int kp = li / sg.Nsrc, n = li - kp * sg.Nsrc;
    float a = sg.src[(size_t)(2 * kp) * sg.Nsrc + n];
    float b = sg.src[(size_t)(2 * kp + 1) * sg.Nsrc + n];
    uint32_t h, l;
    split2(a, b, h, l);
    sg.dh[(size_t)kp * sg.Ndst + sg.coff + n] = h;
    sg.dl[(size_t)kp * sg.Ndst + sg.coff + n] = l;
}

__global__ void s_init_kernel(float* __restrict__ s, const float* __restrict__ b2)
{
    int idx = blockIdx.x * blockDim.x + threadIdx.x;
    if (idx < CA) s[idx] = b2[0];
}

// ---------------- pointer-pair arg block (z selects encoder) -------------------
struct G2 {
    const uint32_t *Ah0, *Al0, *Bh0, *Bl0;
    const uint32_t *Ah1, *Al1, *Bh1, *Bl1;
    const float *bias0, *bias1, *Res0, *Res1;
    float *Cm0, *Cm1;
    uint32_t *Ch0, *Cl0, *Ch1, *Cl1;
};

// ---------------- split-bf16 tensor GEMM: 128x128 tile, cp.async staging ------
template <bool RELU, bool BIAS, bool RES, bool GATHER, bool OUTF32, bool SPLIT, bool SCORE>
__global__ __launch_bounds__(256, 2)
void tgemm_kernel(G2 g, const float* __restrict__ w2, float* __restrict__ sout,
                  int M, int N, int K,
                  const int* __restrict__ gl, const int* __restrict__ ga)
{
    __shared__ uint32_t As_h[2][128][12];
    __shared__ uint32_t As_l[2][128][12];
    __shared__ uint32_t Bs_h[2][8][136];
    __shared__ uint32_t Bs_l[2][8][136];

    const int z = blockIdx.z;
    const uint32_t* __restrict__ Ah = z ? g.Ah1 : g.Ah0;
    const uint32_t* __restrict__ Al = z ? g.Al1 : g.Al0;
    const uint32_t* __restrict__ Bh = z ? g.Bh1 : g.Bh0;
    const uint32_t* __restrict__ Bl = z ? g.Bl1 : g.Bl0;
    const float* __restrict__ bias  = z ? g.bias1 : g.bias0;
    const float* __restrict__ Res   = z ? g.Res1 : g.Res0;
    float* __restrict__ Cm          = z ? g.Cm1 : g.Cm0;
    uint32_t* __restrict__ Ch       = z ? g.Ch1 : g.Ch0;
    uint32_t* __restrict__ Cl       = z ? g.Cl1 : g.Cl0;

    const int tid  = threadIdx.x;
    const int lane = tid & 31;
    const int wid  = tid >> 5;
    const int warp_m = wid & 3;
    const int warp_n = wid >> 2;
    const int m0 = blockIdx.y * 128, n0 = blockIdx.x * 128;
    const int r = lane >> 2, c = lane & 3;
    const int Khalf = K >> 1;

    int arow[2], akp2[2], bkp[2], bcol2[2];
    #pragma unroll
    for (int i = 0; i < 2; i++) {
        int idx = tid + i * 256;
        arow[i] = idx >> 2;  akp2[i]  = (idx & 3) << 1;
        bkp[i]  = idx >> 6;  bcol2[i] = (idx & 63) << 1;
    }

    int grow_l[2], grow_a[2];
    if (GATHER) {
        #pragma unroll
        for (int i = 0; i < 2; i++) {
            grow_l[i] = gl[m0 + arow[i]];
            grow_a[i] = ga[m0 + arow[i]];
        }
    }

    // precomputed smem byte addresses (per buffer delta is constant array stride)
    uint32_t ah_dst[2], al_dst[2], bh_dst[2], bl_dst[2];
    #pragma unroll
    for (int i = 0; i < 2; i++) {
        ah_dst[i] = (uint32_t)__cvta_generic_to_shared(&As_h[0][arow[i]][akp2[i]]);
        al_dst[i] = (uint32_t)__cvta_generic_to_shared(&As_l[0][arow[i]][akp2[i]]);
        bh_dst[i] = (uint32_t)__cvta_generic_to_shared(&Bs_h[0][bkp[i]][bcol2[i]]);
        bl_dst[i] = (uint32_t)__cvta_generic_to_shared(&Bs_l[0][bkp[i]][bcol2[i]]);
    }
    const uint32_t adelta = 128 * 12 * 4;   // bytes per A buffer
    const uint32_t bdelta = 8 * 136 * 4;    // bytes per B buffer

    float acc[2][8][4] = {};

    auto issue_tile = [&](int buf, int k0) {
        const int kpb = k0 >> 1;
        #pragma unroll
        for (int i = 0; i < 2; i++) {
            size_t aaddr;
            if (GATHER) {
                const int kglob = k0 + akp2[i] * 2;
                const int src = (kglob < 256) ? grow_l[i] : grow_a[i];
                aaddr = (size_t)src * 128 + ((kpb + akp2[i]) & 127);
            } else {
                aaddr = (size_t)(m0 + arow[i]) * Khalf + kpb + akp2[i];
            }
            CP_ASYNC8(ah_dst[i] + buf * adelta, &Ah[aaddr]);
            CP_ASYNC8(al_dst[i] + buf * adelta, &Al[aaddr]);
            const size_t baddr = (size_t)(kpb + bkp[i]) * N + n0 + bcol2[i];
            CP_ASYNC8(bh_dst[i] + buf * bdelta, &Bh[baddr]);
            CP_ASYNC8(bl_dst[i] + buf * bdelta, &Bl[baddr]);
        }
    };

    issue_tile(0, 0);
    CP_COMMIT();
    CP_WAIT0();
    __syncthreads();

    const int ntiles = K >> 4;
    for (int t = 0; t < ntiles; t++) {
        const int cur = t & 1;
        if (t + 1 < ntiles) {
            issue_tile(cur ^ 1, (t + 1) << 4);
            CP_COMMIT();
        }

        uint32_t a_h[2][4], a_l[2][4], b_h[8][2], b_l[8][2];
        #pragma unroll
        for (int mt = 0; mt < 2; mt++) {
            const int row = warp_m * 32 + mt * 16 + r;
            a_h[mt][0] = As_h[cur][row][c];
            a_h[mt][1] = As_h[cur][row + 8][c];
            a_h[mt][2] = As_h[cur][row][c + 4];
            a_h[mt][3] = As_h[cur][row + 8][c + 4];
            a_l[mt][0] = As_l[cur][row][c];
            a_l[mt][1] = As_l[cur][row + 8][c];
            a_l[mt][2] = As_l[cur][row][c + 4];
            a_l[mt][3] = As_l[cur][row + 8][c + 4];
        }
        #pragma unroll
        for (int nt = 0; nt < 8; nt++) {
            const int col = warp_n * 64 + nt * 8 + r;
            b_h[nt][0] = Bs_h[cur][c][col];
            b_h[nt][1] = Bs_h[cur][c + 4][col];
            b_l[nt][0] = Bs_l[cur][c][col];
            b_l[nt][1] = Bs_l[cur][c + 4][col];
        }

        #pragma unroll
        for (int mt = 0; mt < 2; mt++)
            #pragma unroll
            for (int nt = 0; nt < 8; nt++) {
                mma_bf16(acc[mt][nt], a_h[mt], b_h[nt]);
                mma_bf16(acc[mt][nt], a_h[mt], b_l[nt]);
                mma_bf16(acc[mt][nt], a_l[mt], b_h[nt]);
            }

        if (t + 1 < ntiles) {
            CP_WAIT0();
            __syncthreads();
        }
    }

    float partial[4] = {0.f, 0.f, 0.f, 0.f};

    #pragma unroll
    for (int mt = 0; mt < 2; mt++) {
        #pragma unroll
        for (int nt = 0; nt < 8; nt++) {
            const int row0 = m0 + warp_m * 32 + mt * 16 + r;
            const int col  = n0 + warp_n * 64 + nt * 8 + 2 * c;
            #pragma unroll
            for (int h = 0; h < 2; h++) {
                float2 v = make_float2(acc[mt][nt][h * 2], acc[mt][nt][h * 2 + 1]);
                if (BIAS) {
                    const float2 bb = *(const float2*)&bias[col];
                    v.x += bb.x; v.y += bb.y;
                }
                if (RELU) { v.x = fmaxf(v.x, 0.f); v.y = fmaxf(v.y, 0.f); }
                const int row = row0 + h * 8;
                const size_t off = (size_t)row * N + col;
                if (RES) {
                    const float2 rr = *(const float2*)&Res[off];
                    v.x += rr.x; v.y += rr.y;
                }
                if (SCORE) {
                    const float2 ww = *(const float2*)&w2[col];
                    partial[mt * 2 + h] += v.x * ww.x + v.y * ww.y;
                }
                if (OUTF32) *(float2*)&Cm[off] = v;
                if (SPLIT) {
                    uint32_t hw, lw;
                    split2(v.x, v.y, hw, lw);
                    Ch[(size_t)row * (N >> 1) + (col >> 1)] = hw;
                    Cl[(size_t)row * (N >> 1) + (col >> 1)] = lw;
                }
            }
        }
    }

    if (SCORE) {
        #pragma unroll
        for (int mt = 0; mt < 2; mt++)
            #pragma unroll
            for (int h = 0; h < 2; h++) {
                float p = partial[mt * 2 + h];
                p += __shfl_xor_sync(0xffffffffu, p, 1);
                p += __shfl_xor_sync(0xffffffffu, p, 2);
                if ((lane & 3) == 0) {
                    const int row = m0 + warp_m * 32 + mt * 16 + r + h * 8;
                    atomicAdd(&sout[row], p);
                }
            }
    }
}

// ---------------- DAG softmax + weighted ancestor sum --------------------------
__global__ void dag_softmax_kernel(const float* __restrict__ s, const float* __restrict__ mask,
                                   const int* __restrict__ anc, const float* __restrict__ emb,
                                   float* __restrict__ dag)
{
    int gw = (blockIdx.x * blockDim.x + threadIdx.x) >> 5;
    int lane = threadIdx.x & 31;
    if (gw >= C) return;
    float sv = -3.0e38f;
    int av = 0;
    if (lane < 8) {
        float m = mask[gw * 8 + lane];
        sv = s[gw * 8 + lane] + (1.f - m) * VERY_NEG;
        av = anc[gw * 8 + lane];
    }
    float mx = sv;
    #pragma unroll
    for (int off = 4; off; off >>= 1) mx = fmaxf(mx, __shfl_xor_sync(0xffffffffu, mx, off));
    float e = (lane < 8) ? __expf(sv - mx) : 0.f;
    float su = e;
    #pragma unroll
    for (int off = 4; off; off >>= 1) su += __shfl_xor_sync(0xffffffffu, su, off);
    float wv = e / su;
    float w8[8];
    int   a8[8];
    #pragma unroll
    for (int a = 0; a < 8; a++) {
        w8[a] = __shfl_sync(0xffffffffu, wv, a);
        a8[a] = __shfl_sync(0xffffffffu, av, a);
    }
    const float4* e4 = (const float4*)emb;
    #pragma unroll
    for (int rep = 0; rep < 2; rep++) {
        int f4i = lane + rep * 32;
        float4 acc = make_float4(0.f, 0.f, 0.f, 0.f);
        #pragma unroll
        for (int a = 0; a < 8; a++) {
            float4 v = e4[(size_t)a8[a] * 64 + f4i];
            acc.x = fmaf(w8[a], v.x, acc.x);
            acc.y = fmaf(w8[a], v.y, acc.y);
            acc.z = fmaf(w8[a], v.z, acc.z);
            acc.w = fmaf(w8[a], v.w, acc.w);
        }
        ((float4*)dag)[(size_t)gw * 64 + f4i] = acc;
    }
}

__global__ void embed_gather_kernel(const int* __restrict__ ids, const float* __restrict__ embw,
                                    const float* __restrict__ dag,
                                    float* __restrict__ xv, float* __restrict__ xd,
                                    uint32_t* __restrict__ xvh, uint32_t* __restrict__ xvl,
                                    uint32_t* __restrict__ xdh, uint32_t* __restrict__ xdl)
{
    int idx = blockIdx.x * blockDim.x + threadIdx.x;
    if (idx >= BS * 64) return;
    int bs = idx >> 6, h4 = idx & 63;
    int id = ids[bs];
    float4 vv = ((const float4*)embw)[(size_t)id * 64 + h4];
    ((float4*)xv)[(size_t)bs * 64 + h4] = vv;
    float4 dv = make_float4(0.f, 0.f, 0.f, 0.f);
    if (id > 0) dv = ((const float4*)dag)[(size_t)(id - 1) * 64 + h4];
    ((float4*)xd)[(size_t)bs * 64 + h4] = dv;

    uint32_t h0, l0, h1, l1;
    split2(vv.x, vv.y, h0, l0);
    split2(vv.z, vv.w, h1, l1);
    xvh[(size_t)bs * 128 + h4 * 2]     = h0;
    xvh[(size_t)bs * 128 + h4 * 2 + 1] = h1;
    xvl[(size_t)bs * 128 + h4 * 2]     = l0;
    xvl[(size_t)bs * 128 + h4 * 2 + 1] = l1;
    split2(dv.x, dv.y, h0, l0);
    split2(dv.z, dv.w, h1, l1);
    xdh[(size_t)bs * 128 + h4 * 2]     = h0;
    xdh[(size_t)bs * 128 + h4 * 2 + 1] = h1;
    xdl[(size_t)bs * 128 + h4 * 2]     = l0;
    xdl[(size_t)bs * 128 + h4 * 2 + 1] = l1;
}

// ---------------- attention: SIMT chunked online softmax (z selects) ----------
struct A2 {
    const float *qkv0, *qkv1;
    uint32_t *h0, *l0, *h1, *l1;
};

__global__ void attention_kernel(A2 g, const float* __restrict__ cmask)
{
    extern __shared__ float sm[];
    float* Ks = sm;
    float* Vs = sm + S * Dh;
    float* madd = Vs + S * Dh;
    const int h = blockIdx.x, b = blockIdx.y, z = blockIdx.z;
    const float* __restrict__ QKV = z ? g.qkv1 : g.qkv0;
    uint32_t* __restrict__ cth = z ? g.h1 : g.h0;
    uint32_t* __restrict__ ctl = z ? g.l1 : g.l0;
    const int tid = threadIdx.x;
    const size_t rowbase = (size_t)b * S * QKVN;
    const int qo = h * Dh, ko = H + h * Dh, vo = 2 * H + h * Dh;

    for (int i = tid; i < S * 8; i += 256) {
        int row = i >> 3, slot = (i & 7) << 2;
        *(float4*)&Ks[row * Dh + slot] = *(const float4*)&QKV[rowbase + (size_t)row * QKVN + ko + slot];
        *(float4*)&Vs[row * Dh + slot] = *(const float4*)&QKV[rowbase + (size_t)row * QKVN + vo + slot];
    }
    madd[tid] = (1.0f - cmask[b * S + tid]) * VERY_NEG;
    __syncthreads();

    float q[32];
    const float* qp = &QKV[rowbase + (size_t)tid * QKVN + qo];
    #pragma unroll
    for (int i = 0; i < 32; i += 4) {
        float4 t = *(const float4*)&qp[i];
        q[i] = t.x; q[i + 1] = t.y; q[i + 2] = t.z; q[i + 3] = t.w;
    }
    const float scale = rsqrtf(32.0f);
    float m = -INFINITY, l = 0.f, o[32];
    #pragma unroll
    for (int i = 0; i < 32; i++) o[i] = 0.f;

    for (int k0 = 0; k0 < S; k0 += 16) {
        float sc[16];
        float cm = -INFINITY;
        #pragma unroll
        for (int kk = 0; kk < 16; kk++) {
            const float* kr = &Ks[(k0 + kk) * Dh];
            float d = 0.f;
            #pragma unroll
            for (int i = 0; i < 32; i++) d = fmaf(q[i], kr[i], d);
            sc[kk] = d * scale + madd[k0 + kk];
            cm = fmaxf(cm, sc[kk]);
        }
        const float mn = fmaxf(m, cm);
        const float corr = __expf(m - mn);
        l *= corr;
        #pragma unroll
        for (int i = 0; i < 32; i++) o[i] *= corr;
        #pragma unroll
        for (int kk = 0; kk < 16; kk++) {
            const float p = __expf(sc[kk] - mn);
            l += p;
            const float* vr = &Vs[(k0 + kk) * Dh];
            #pragma unroll
            for (int i = 0; i < 32; i++) o[i] = fmaf(p, vr[i], o[i]);
        }
        m = mn;
    }
    const float inv = 1.0f / l;
    const size_t prow = (size_t)(b * S + tid) * 128 + h * 16;
    #pragma unroll
    for (int i = 0; i < 32; i += 2) {
        uint32_t hw, lw;
        split2(o[i] * inv, o[i + 1] * inv, hw, lw);
        cth[prow + i / 2] = hw;
        ctl[prow + i / 2] = lw;
    }
}

// ---------------- pooling ------------------------------------------------------
__global__ void pool_kernel(const float* __restrict__ x, const float* __restrict__ cmask,
                            const float* __restrict__ pw, const float* __restrict__ pb,
                            float* __restrict__ out)
{
    __shared__ float spw[H];
    __shared__ float sc[S];
    __shared__ float red[8];
    const int b = blockIdx.x, tid = threadIdx.x;
    const int lane = tid & 31, w = tid >> 5;
    spw[tid] = pw[tid];
    __syncthreads();

    for (int row = w; row < S; row += 8) {
        const float* xp = &x[((size_t)b * S + row) * H];
        float4 a0 = *(const float4*)&xp[lane * 4];
        float4 a1 = *(const float4*)&xp[128 + lane * 4];
        float acc = a0.x * spw[lane * 4 + 0] + a0.y * spw[lane * 4 + 1]
                  + a0.z * spw[lane * 4 + 2] + a0.w * spw[lane * 4 + 3]
                  + a1.x * spw[128 + lane * 4 + 0] + a1.y * spw[128 + lane * 4 + 1]
                  + a1.z * spw[128 + lane * 4 + 2] + a1.w * spw[128 + lane * 4 + 3];
        #pragma unroll
        for (int off = 16; off; off >>= 1) acc += __shfl_xor_sync(0xffffffffu, acc, off);
        if (lane == 0)
            sc[row] = acc + pb[0] + (1.f - cmask[b * S + row]) * VERY_NEG;
    }
    __syncthreads();

    float v = sc[tid];
    float mx = v;
    #pragma unroll
    for (int off = 16; off; off >>= 1) mx = fmaxf(mx, __shfl_xor_sync(0xffffffffu, mx, off));
    if (lane == 0) red[w] = mx;
    __syncthreads();
    float bm = red[0];
    #pragma unroll
    for (int i = 1; i < 8; i++) bm = fmaxf(bm, red[i]);
    __syncthreads();
    float e = __expf(v - bm);
    float su = e;
    #pragma unroll
    for (int off = 16; off; off >>= 1) su += __shfl_xor_sync(0xffffffffu, su, off);
    if (lane == 0) red[w] = su;
    __syncthreads();
    float tot = 0.f;
    #pragma unroll
    for (int i = 0; i < 8; i++) tot += red[i];
    sc[tid] = e / tot;
    __syncthreads();

    float acc = 0.f;
    for (int ss = 0; ss < S; ss++)
        acc = fmaf(sc[ss], x[((size_t)b * S + ss) * H + tid], acc);
    out[(size_t)b * H + tid] = acc;
}

// ---------------- host ----------------------------------------------------------
extern "C" void kernel_launch(void* const* d_in, const int* in_sizes, int n_in,
                              void* d_out, int out_size)
{
    const int*   input_ids   = (const int*)d_in[0];
    const float* code_mask   = (const float*)d_in[1];
    const int*   dx_leaves   = (const int*)d_in[2];
    const int*   dx_anc      = (const int*)d_in[3];
    const float* dx_mask     = (const float*)d_in[4];
    const float* embed_init  = (const float*)d_in[5];
    const float* embed_inp   = (const float*)d_in[6];
    const float* attn_w1     = (const float*)d_in[7];
    const float* attn_b1     = (const float*)d_in[8];
    const float* attn_w2     = (const float*)d_in[9];
    const float* attn_b2     = (const float*)d_in[10];
    const float* pool_w      = (const float*)d_in[11];
    const float* pool_b      = (const float*)d_in[12];
    const float* enc_w[2][8];
    for (int z = 0; z < 2; z++)
        for (int j = 0; j < 8; j++)
            enc_w[z][j] = (const float*)d_in[13 + z * 8 + j];
    float* out = (float*)d_out;

    uint32_t *eh, *el, *xvh, *xvl, *xdh, *xdl, *w1h, *w1l;
    uint32_t *cth[2], *ctl[2], *th[2], *tl[2], *fh[2], *fl[2];
    uint32_t *wqkvh[2], *wqkvl[2], *woh[2], *wol[2], *f1h[2], *f1l[2], *f2h[2], *f2l[2];
    float *s, *dag, *xv, *xd, *xdo, *qkv[2], *t[2];
    {
        char* p;
        cudaGetSymbolAddress((void**)&eh, g_eh);   cudaGetSymbolAddress((void**)&el, g_el);
        cudaGetSymbolAddress((void**)&s, g_s);     cudaGetSymbolAddress((void**)&dag, g_dag);
        cudaGetSymbolAddress((void**)&xv, g_xv);   cudaGetSymbolAddress((void**)&xd, g_xd);
        cudaGetSymbolAddress((void**)&xvh, g_xvh); cudaGetSymbolAddress((void**)&xvl, g_xvl);
        cudaGetSymbolAddress((void**)&xdh, g_xdh); cudaGetSymbolAddress((void**)&xdl, g_xdl);
        cudaGetSymbolAddress((void**)&xdo, g_xdo);
        cudaGetSymbolAddress((void**)&w1h, g_w1h); cudaGetSymbolAddress((void**)&w1l, g_w1l);
        cudaGetSymbolAddress((void**)&p, g_qkv);   qkv[0] = (float*)p;    qkv[1] = qkv[0] + (size_t)BS * QKVN;
        cudaGetSymbolAddress((void**)&p, g_t);     t[0] = (float*)p;      t[1] = t[0] + (size_t)BS * H;
        cudaGetSymbolAddress((void**)&p, g_cth);   cth[0] = (uint32_t*)p; cth[1] = cth[0] + (size_t)BS * 128;
        cudaGetSymbolAddress((void**)&p, g_ctl);   ctl[0] = (uint32_t*)p; ctl[1] = ctl[0] + (size_t)BS * 128;
        cudaGetSymbolAddress((void**)&p, g_th);    th[0] = (uint32_t*)p;  th[1] = th[0] + (size_t)BS * 128;
        cudaGetSymbolAddress((void**)&p, g_tl);    tl[0] = (uint32_t*)p;  tl[1] = tl[0] + (size_t)BS * 128;
        cudaGetSymbolAddress((void**)&p, g_fh);    fh[0] = (uint32_t*)p;  fh[1] = fh[0] + (size_t)BS * 512;
        cudaGetSymbolAddress((void**)&p, g_fl);    fl[0] = (uint32_t*)p;  fl[1] = fl[0] + (size_t)BS * 512;
        cudaGetSymbolAddress((void**)&p, g_wqkvh); wqkvh[0] = (uint32_t*)p; wqkvh[1] = wqkvh[0] + 128 * QKVN;
        cudaGetSymbolAddress((void**)&p, g_wqkvl); wqkvl[0] = (uint32_t*)p; wqkvl[1] = wqkvl[0] + 128 * QKVN;
        cudaGetSymbolAddress((void**)&p, g_woh);   woh[0] = (uint32_t*)p;   woh[1] = woh[0] + 128 * 256;
        cudaGetSymbolAddress((void**)&p, g_wol);   wol[0] = (uint32_t*)p;   wol[1] = wol[0] + 128 * 256;
        cudaGetSymbolAddress((void**)&p, g_f1h);   f1h[0] = (uint32_t*)p;   f1h[1] = f1h[0] + 128 * 1024;
        cudaGetSymbolAddress((void**)&p, g_f1l);   f1l[0] = (uint32_t*)p;   f1l[1] = f1l[0] + 128 * 1024;
        cudaGetSymbolAddress((void**)&p, g_f2h);   f2h[0] = (uint32_t*)p;   f2h[1] = f2h[0] + 512 * 256;
        cudaGetSymbolAddress((void**)&p, g_f2l);   f2l[0] = (uint32_t*)p;   f2l[1] = f2l[0] + 512 * 256;
    }

    const int asmem = (2 * S * Dh + S) * (int)sizeof(float);
    cudaFuncSetAttribute(attention_kernel, cudaFuncAttributeMaxDynamicSharedMemorySize, asmem);

    const int PT = 256;
    pack_contig_kernel<<<(NODES1 * 128 + PT - 1) / PT, PT>>>(embed_init, eh, el, NODES1 * 128);
    s_init_kernel<<<(CA + PT - 1) / PT, PT>>>(s, attn_b2);

    // merged weight packing: 13 segments, one launch
    {
        PackAll pa{};
        int cur = 0, si = 0;
        auto add = [&](const float* src, uint32_t* dh, uint32_t* dl,
                       int Khalf, int Nsrc, int Ndst, int coff) {
            pa.seg[si] = {src, dh, dl, Khalf, Nsrc, Ndst, coff, cur};
            cur += Khalf * Nsrc;
            si++;
        };
        add(attn_w1, w1h, w1l, 256, 256, 256, 0);
        for (int z = 0; z < 2; z++) {
            add(enc_w[z][0], wqkvh[z], wqkvl[z], 128, 256, QKVN, 0);
            add(enc_w[z][1], wqkvh[z], wqkvl[z], 128, 256, QKVN, 256);
            add(enc_w[z][2], wqkvh[z], wqkvl[z], 128, 256, QKVN, 512);
            add(enc_w[z][3], woh[z], wol[z], 128, 256, 256, 0);
            add(enc_w[z][4], f1h[z], f1l[z], 128, 1024, 1024, 0);
            add(enc_w[z][6], f2h[z], f2l[z], 512, 256, 256, 0);
        }
        pa.total = cur;
        pack_all_kernel<<<(cur + PT - 1) / PT, PT>>>(pa);
    }

    // DAG MLP: gathered A + fused score
    {
        G2 g{};
        g.Ah0 = g.Ah1 = eh;  g.Al0 = g.Al1 = el;
        g.Bh0 = g.Bh1 = w1h; g.Bl0 = g.Bl1 = w1l;
        g.bias0 = g.bias1 = attn_b1;
        tgemm_kernel<true, true, false, true, false, false, true><<<dim3(2, CA / 128, 1), 256>>>(
            g, attn_w2, s, CA, 256, 512, dx_leaves, dx_anc);
    }
    dag_softmax_kernel<<<C / 8, 256>>>(s, dx_mask, dx_anc, embed_init, dag);
    embed_gather_kernel<<<(BS * 64 + PT - 1) / PT, PT>>>(input_ids, embed_inp, dag,
                                                         xv, xd, xvh, xvl, xdh, xdl);

    // --- both encoders batched over gridDim.z ---
    {
        G2 g{};
        g.Ah0 = xvh; g.Al0 = xvl; g.Ah1 = xdh; g.Al1 = xdl;
        g.Bh0 = wqkvh[0]; g.Bl0 = wqkvl[0]; g.Bh1 = wqkvh[1]; g.Bl1 = wqkvl[1];
        g.Cm0 = qkv[0]; g.Cm1 = qkv[1];
        tgemm_kernel<false, false, false, false, true, false, false><<<dim3(QKVN / 128, BS / 128, 2), 256>>>(
            g, nullptr, nullptr, BS, QKVN, H, nullptr, nullptr);
    }
    {
        A2 a{qkv[0], qkv[1], cth[0], ctl[0], cth[1], ctl[1]};
        attention_kernel<<<dim3(NH, Bz, 2), 256, asmem>>>(a, code_mask);
    }
    {
        G2 g{};
        g.Ah0 = cth[0]; g.Al0 = ctl[0]; g.Ah1 = cth[1]; g.Al1 = ctl[1];
        g.Bh0 = woh[0]; g.Bl0 = wol[0]; g.Bh1 = woh[1]; g.Bl1 = wol[1];
        g.Res0 = xv; g.Res1 = xd;
        g.Cm0 = t[0]; g.Cm1 = t[1];
        g.Ch0 = th[0]; g.Cl0 = tl[0]; g.Ch1 = th[1]; g.Cl1 = tl[1];
        tgemm_kernel<false, false, true, false, true, true, false><<<dim3(2, BS / 128, 2), 256>>>(
            g, nullptr, nullptr, BS, H, H, nullptr, nullptr);
    }
    {
        G2 g{};
        g.Ah0 = th[0]; g.Al0 = tl[0]; g.Ah1 = th[1]; g.Al1 = tl[1];
        g.Bh0 = f1h[0]; g.Bl0 = f1l[0]; g.Bh1 = f1h[1]; g.Bl1 = f1l[1];
        g.bias0 = enc_w[0][5]; g.bias1 = enc_w[1][5];
        g.Ch0 = fh[0]; g.Cl0 = fl[0]; g.Ch1 = fh[1]; g.Cl1 = fl[1];
        tgemm_kernel<true, true, false, false, false, true, false><<<dim3(FF / 128, BS / 128, 2), 256>>>(
            g, nullptr, nullptr, BS, FF, H, nullptr, nullptr);
    }
    {
        G2 g{};
        g.Ah0 = fh[0]; g.Al0 = fl[0]; g.Ah1 = fh[1]; g.Al1 = fl[1];
        g.Bh0 = f2h[0]; g.Bl0 = f2l[0]; g.Bh1 = f2h[1]; g.Bl1 = f2l[1];
        g.bias0 = enc_w[0][7]; g.bias1 = enc_w[1][7];
        g.Res0 = t[0]; g.Res1 = t[1];
        g.Cm0 = out; g.Cm1 = xdo;
        tgemm_kernel<false, true, true, false, true, false, false><<<dim3(2, BS / 128, 2), 256>>>(
            g, nullptr, nullptr, BS, H, FF, nullptr, nullptr);
    }

    pool_kernel<<<Bz, 256>>>(xdo, code_mask, pool_w, pool_b, out + (size_t)BS * H);
}

// round 14
// speedup vs baseline: 1.3538x; 1.1350x over previous
#include <cuda_runtime.h>
#include <cuda_bf16.h>
#include <math.h>
#include <stdint.h>

#define VERY_NEG (-1e30f)

constexpr int Bz = 128;
constexpr int S  = 256;
constexpr int H  = 256;
constexpr int NH = 8;
constexpr int Dh = 32;
constexpr int C  = 20000;
constexpr int A  = 8;
constexpr int BS = Bz * S;
constexpr int CA = C * A;
constexpr int FF = 4 * H;
constexpr int NODES1 = 25001;
constexpr int QKVN = 3 * H;

// dynamic smem: 3 stages x (A 128x12 + B 8x136) x {h,l}
constexpr int AW = 128 * 12;          // words per A stage (per h/l)
constexpr int BW = 8 * 136;           // words per B stage
constexpr int GSM = 3 * (AW + BW) * 2 * 4;   // 62976 bytes

// ---------------- scratch ------------------------------------------------------
__device__ uint32_t g_eh [(size_t)NODES1 * 128];
__device__ uint32_t g_el [(size_t)NODES1 * 128];
__device__ float    g_s  [CA];
__device__ float    g_dag[(size_t)C * H];
__device__ float    g_xv [(size_t)BS * H];
__device__ float    g_xd [(size_t)BS * H];
__device__ uint32_t g_xvh[(size_t)BS * 128], g_xvl[(size_t)BS * 128];
__device__ uint32_t g_xdh[(size_t)BS * 128], g_xdl[(size_t)BS * 128];
__device__ float    g_qkv[2][(size_t)BS * QKVN];
__device__ uint32_t g_cth[2][(size_t)BS * 128], g_ctl[2][(size_t)BS * 128];
__device__ float    g_t  [2][(size_t)BS * H];
__device__ uint32_t g_th [2][(size_t)BS * 128], g_tl [2][(size_t)BS * 128];
__device__ uint32_t g_fh [2][(size_t)BS * 512], g_fl [2][(size_t)BS * 512];
__device__ float    g_xdo[(size_t)BS * H];
__device__ uint32_t g_wqkvh[2][128 * QKVN], g_wqkvl[2][128 * QKVN];
__device__ uint32_t g_woh [2][128 * 256],  g_wol [2][128 * 256];
__device__ uint32_t g_f1h [2][128 * 1024], g_f1l [2][128 * 1024];
__device__ uint32_t g_f2h [2][512 * 256],  g_f2l [2][512 * 256];
__device__ uint32_t g_w1h [256 * 256],  g_w1l [256 * 256];

// ---------------- helpers ------------------------------------------------------
__device__ __forceinline__ void mma_bf16(float* c, const uint32_t* a, const uint32_t* b) {
    asm volatile(
        "mma.sync.aligned.m16n8k16.row.col.f32.bf16.bf16.f32 "
        "{%0,%1,%2,%3}, {%4,%5,%6,%7}, {%8,%9}, {%0,%1,%2,%3};\n"
        : "+f"(c[0]), "+f"(c[1]), "+f"(c[2]), "+f"(c[3])
        : "r"(a[0]), "r"(a[1]), "r"(a[2]), "r"(a[3]),
          "r"(b[0]), "r"(b[1]));
}

__device__ __forceinline__ void split2(float x0, float x1, uint32_t& hi, uint32_t& lo) {
    __nv_bfloat16 h0 = __float2bfloat16_rn(x0);
    __nv_bfloat16 h1 = __float2bfloat16_rn(x1);
    __nv_bfloat16 l0 = __float2bfloat16_rn(x0 - __bfloat162float(h0));
    __nv_bfloat16 l1 = __float2bfloat16_rn(x1 - __bfloat162float(h1));
    hi = ((uint32_t)__bfloat16_as_ushort(h1) << 16) | __bfloat16_as_ushort(h0);
    lo = ((uint32_t)__bfloat16_as_ushort(l1) << 16) | __bfloat16_as_ushort(l0);
}

#define CP_ASYNC16(dst, src) \
    asm volatile("cp.async.cg.shared.global [%0], [%1], 16;" :: "r"(dst), "l"(src) : "memory")
#define CP_COMMIT()  asm volatile("cp.async.commit_group;" ::: "memory")
#define CP_WAIT0()   asm volatile("cp.async.wait_group 0;" ::: "memory")
#define CP_WAIT1()   asm volatile("cp.async.wait_group 1;" ::: "memory")

__global__ void pack_contig_kernel(const float* __restrict__ src, uint32_t* __restrict__ dh,
                                   uint32_t* __restrict__ dl, int n2)
{
    int idx = blockIdx.x * blockDim.x + threadIdx.x;
    if (idx >= n2) return;
    float2 v = ((const float2*)src)[idx];
    uint32_t h, l;
    split2(v.x, v.y, h, l);
    dh[idx] = h; dl[idx] = l;
}

struct PackSeg {
    const float* src;
    uint32_t *dh, *dl;
    int Khalf, Nsrc, Ndst, coff, start;
};
struct PackAll { PackSeg seg[13]; int total; };

__global__ void pack_all_kernel(PackAll pa)
{
    int idx = blockIdx.x * blockDim.x + threadIdx.x;
    if (idx >= pa.total) return;
    int si = 0;
    #pragma unroll
    for (int i = 1; i < 13; i++)
        if (idx >= pa.seg[i].start) si = i;
    const PackSeg& sg = pa.seg[si];
    int li = idx - sg.start;
    int kp = li / sg.Nsrc, n = li - kp * sg.Nsrc;
    float a = sg.src[(size_t)(2 * kp) * sg.Nsrc + n];
    float b = sg.src[(size_t)(2 * kp + 1) * sg.Nsrc + n];
    uint32_t h, l;
    split2(a, b, h, l);
    sg.dh[(size_t)kp * sg.Ndst + sg.coff + n] = h;
    sg.dl[(size_t)kp * sg.Ndst + sg.coff + n] = l;
}

__global__ void s_init_kernel(float* __restrict__ s, const float* __restrict__ b2)
{
    int idx = blockIdx.x * blockDim.x + threadIdx.x;
    if (idx < CA) s[idx] = b2[0];
}

// ---------------- pointer-pair arg block (z selects encoder) -------------------
struct G2 {
    const uint32_t *Ah0, *Al0, *Bh0, *Bl0;
    const uint32_t *Ah1, *Al1, *Bh1, *Bl1;
    const float *bias0, *bias1, *Res0, *Res1;
    float *Cm0, *Cm1;
    uint32_t *Ch0, *Cl0, *Ch1, *Cl1;
};

// ---------------- split-bf16 tensor GEMM: 3-stage cp.async pipeline -----------
template <bool RELU, bool BIAS, bool RES, bool GATHER, bool OUTF32, bool SPLIT, bool SCORE>
__global__ __launch_bounds__(256, 2)
void tgemm_kernel(G2 g, const float* __restrict__ w2, float* __restrict__ sout,
                  int M, int N, int K,
                  const int* __restrict__ gl, const int* __restrict__ ga)
{
    extern __shared__ uint32_t dsm[];
    uint32_t* ASH = dsm;                 // [3][128][12]
    uint32_t* ASL = dsm + 3 * AW;
    uint32_t* BSH = dsm + 6 * AW;        // [3][8][136]
    uint32_t* BSL = dsm + 6 * AW + 3 * BW;

    const int z = blockIdx.z;
    const uint32_t* __restrict__ Ah = z ? g.Ah1 : g.Ah0;
    const uint32_t* __restrict__ Al = z ? g.Al1 : g.Al0;
    const uint32_t* __restrict__ Bh = z ? g.Bh1 : g.Bh0;
    const uint32_t* __restrict__ Bl = z ? g.Bl1 : g.Bl0;
    const float* __restrict__ bias  = z ? g.bias1 : g.bias0;
    const float* __restrict__ Res   = z ? g.Res1 : g.Res0;
    float* __restrict__ Cm          = z ? g.Cm1 : g.Cm0;
    uint32_t* __restrict__ Ch       = z ? g.Ch1 : g.Ch0;
    uint32_t* __restrict__ Cl       = z ? g.Cl1 : g.Cl0;

    const int tid  = threadIdx.x;
    const int lane = tid & 31;
    const int wid  = tid >> 5;
    const int warp_m = wid & 3;
    const int warp_n = wid >> 2;
    const int m0 = blockIdx.y * 128, n0 = blockIdx.x * 128;
    const int r = lane >> 2, c = lane & 3;
    const int Khalf = K >> 1;

    // 16B copy mapping: A row/half, B kprow/col4
    const int arow   = tid >> 1;
    const int ahalf4 = (tid & 1) << 2;     // kpair offset 0 or 4
    const int bkp    = tid >> 5;           // 0..7
    const int bcol4  = (tid & 31) << 2;    // 0..124

    int grow_l = 0, grow_a = 0;
    if (GATHER) {
        grow_l = gl[m0 + arow];
        grow_a = ga[m0 + arow];
    }

    uint32_t a_h_dst = (uint32_t)__cvta_generic_to_shared(&ASH[arow * 12 + ahalf4]);
    uint32_t a_l_dst = (uint32_t)__cvta_generic_to_shared(&ASL[arow * 12 + ahalf4]);
    uint32_t b_h_dst = (uint32_t)__cvta_generic_to_shared(&BSH[bkp * 136 + bcol4]);
    uint32_t b_l_dst = (uint32_t)__cvta_generic_to_shared(&BSL[bkp * 136 + bcol4]);

    float acc[2][8][4] = {};

    auto issue_tile = [&](int buf, int k0) {
        const int kpb = k0 >> 1;
        size_t aaddr;
        if (GATHER) {
            const int kglob = k0 + ahalf4 * 2;
            const int src = (kglob < 256) ? grow_l : grow_a;
            aaddr = (size_t)src * 128 + ((kpb + ahalf4) & 127);
        } else {
            aaddr = (size_t)(m0 + arow) * Khalf + kpb + ahalf4;
        }
        CP_ASYNC16(a_h_dst + buf * (AW * 4), &Ah[aaddr]);
        CP_ASYNC16(a_l_dst + buf * (AW * 4), &Al[aaddr]);
        const size_t baddr = (size_t)(kpb + bkp) * N + n0 + bcol4;
        CP_ASYNC16(b_h_dst + buf * (BW * 4), &Bh[baddr]);
        CP_ASYNC16(b_l_dst + buf * (BW * 4), &Bl[baddr]);
    };

    const int ntiles = K >> 4;
    issue_tile(0, 0);
    CP_COMMIT();
    if (ntiles > 1) { issue_tile(1, 16); CP_COMMIT(); }

    int cur = 0;
    for (int t = 0; t < ntiles; t++) {
        if (t + 1 < ntiles) CP_WAIT1(); else CP_WAIT0();
        __syncthreads();

        uint32_t a_h[2][4], a_l[2][4], b_h[8][2], b_l[8][2];
        const uint32_t* Ahc = ASH + cur * AW;
        const uint32_t* Alc = ASL + cur * AW;
        const uint32_t* Bhc = BSH + cur * BW;
        const uint32_t* Blc = BSL + cur * BW;
        #pragma unroll
        for (int mt = 0; mt < 2; mt++) {
            const int row = warp_m * 32 + mt * 16 + r;
            a_h[mt][0] = Ahc[row * 12 + c];
            a_h[mt][1] = Ahc[(row + 8) * 12 + c];
            a_h[mt][2] = Ahc[row * 12 + c + 4];
            a_h[mt][3] = Ahc[(row + 8) * 12 + c + 4];
            a_l[mt][0] = Alc[row * 12 + c];
            a_l[mt][1] = Alc[(row + 8) * 12 + c];
            a_l[mt][2] = Alc[row * 12 + c + 4];
            a_l[mt][3] = Alc[(row + 8) * 12 + c + 4];
        }
        #pragma unroll
        for (int nt = 0; nt < 8; nt++) {
            const int col = warp_n * 64 + nt * 8 + r;
            b_h[nt][0] = Bhc[c * 136 + col];
            b_h[nt][1] = Bhc[(c + 4) * 136 + col];
            b_l[nt][0] = Blc[c * 136 + col];
            b_l[nt][1] = Blc[(c + 4) * 136 + col];
        }

        if (t + 2 < ntiles) {
            int nxt = cur + 2;
            if (nxt >= 3) nxt -= 3;
            issue_tile(nxt, (t + 2) << 4);
            CP_COMMIT();
        }

        #pragma unroll
        for (int mt = 0; mt < 2; mt++)
            #pragma unroll
            for (int nt = 0; nt < 8; nt++) {
                mma_bf16(acc[mt][nt], a_h[mt], b_h[nt]);
                mma_bf16(acc[mt][nt], a_h[mt], b_l[nt]);
                mma_bf16(acc[mt][nt], a_l[mt], b_h[nt]);
            }

        cur = (cur == 2) ? 0 : cur + 1;
    }

    float partial[4] = {0.f, 0.f, 0.f, 0.f};

    #pragma unroll
    for (int mt = 0; mt < 2; mt++) {
        #pragma unroll
        for (int nt = 0; nt < 8; nt++) {
            const int row0 = m0 + warp_m * 32 + mt * 16 + r;
            const int col  = n0 + warp_n * 64 + nt * 8 + 2 * c;
            #pragma unroll
            for (int h = 0; h < 2; h++) {
                float2 v = make_float2(acc[mt][nt][h * 2], acc[mt][nt][h * 2 + 1]);
                if (BIAS) {
                    const float2 bb = *(const float2*)&bias[col];
                    v.x += bb.x; v.y += bb.y;
                }
                if (RELU) { v.x = fmaxf(v.x, 0.f); v.y = fmaxf(v.y, 0.f); }
                const int row = row0 + h * 8;
                const size_t off = (size_t)row * N + col;
                if (RES) {
                    const float2 rr = *(const float2*)&Res[off];
                    v.x += rr.x; v.y += rr.y;
                }
                if (SCORE) {
                    const float2 ww = *(const float2*)&w2[col];
                    partial[mt * 2 + h] += v.x * ww.x + v.y * ww.y;
                }
                if (OUTF32) *(float2*)&Cm[off] = v;
                if (SPLIT) {
                    uint32_t hw, lw;
                    split2(v.x, v.y, hw, lw);
                    Ch[(size_t)row * (N >> 1) + (col >> 1)] = hw;
                    Cl[(size_t)row * (N >> 1) + (col >> 1)] = lw;
                }
            }
        }
    }

    if (SCORE) {
        #pragma unroll
        for (int mt = 0; mt < 2; mt++)
            #pragma unroll
            for (int h = 0; h < 2; h++) {
                float p = partial[mt * 2 + h];
                p += __shfl_xor_sync(0xffffffffu, p, 1);
                p += __shfl_xor_sync(0xffffffffu, p, 2);
                if ((lane & 3) == 0) {
                    const int row = m0 + warp_m * 32 + mt * 16 + r + h * 8;
                    atomicAdd(&sout[row], p);
                }
            }
    }
}

// ---------------- DAG softmax + weighted ancestor sum --------------------------
__global__ void dag_softmax_kernel(const float* __restrict__ s, const float* __restrict__ mask,
                                   const int* __restrict__ anc, const float* __restrict__ emb,
                                   float* __restrict__ dag)
{
    int gw = (blockIdx.x * blockDim.x + threadIdx.x) >> 5;
    int lane = threadIdx.x & 31;
    if (gw >= C) return;
    float sv = -3.0e38f;
    int av = 0;
    if (lane < 8) {
        float m = mask[gw * 8 + lane];
        sv = s[gw * 8 + lane] + (1.f - m) * VERY_NEG;
        av = anc[gw * 8 + lane];
    }
    float mx = sv;
    #pragma unroll
    for (int off = 4; off; off >>= 1) mx = fmaxf(mx, __shfl_xor_sync(0xffffffffu, mx, off));
    float e = (lane < 8) ? __expf(sv - mx) : 0.f;
    float su = e;
    #pragma unroll
    for (int off = 4; off; off >>= 1) su += __shfl_xor_sync(0xffffffffu, su, off);
    float wv = e / su;
    float w8[8];
    int   a8[8];
    #pragma unroll
    for (int a = 0; a < 8; a++) {
        w8[a] = __shfl_sync(0xffffffffu, wv, a);
        a8[a] = __shfl_sync(0xffffffffu, av, a);
    }
    const float4* e4 = (const float4*)emb;
    #pragma unroll
    for (int rep = 0; rep < 2; rep++) {
        int f4i = lane + rep * 32;
        float4 acc = make_float4(0.f, 0.f, 0.f, 0.f);
        #pragma unroll
        for (int a = 0; a < 8; a++) {
            float4 v = e4[(size_t)a8[a] * 64 + f4i];
            acc.x = fmaf(w8[a], v.x, acc.x);
            acc.y = fmaf(w8[a], v.y, acc.y);
            acc.z = fmaf(w8[a], v.z, acc.z);
            acc.w = fmaf(w8[a], v.w, acc.w);
        }
        ((float4*)dag)[(size_t)gw * 64 + f4i] = acc;
    }
}

__global__ void embed_gather_kernel(const int* __restrict__ ids, const float* __restrict__ embw,
                                    const float* __restrict__ dag,
                                    float* __restrict__ xv, float* __restrict__ xd,
                                    uint32_t* __restrict__ xvh, uint32_t* __restrict__ xvl,
                                    uint32_t* __restrict__ xdh, uint32_t* __restrict__ xdl)
{
    int idx = blockIdx.x * blockDim.x + threadIdx.x;
    if (idx >= BS * 64) return;
    int bs = idx >> 6, h4 = idx & 63;
    int id = ids[bs];
    float4 vv = ((const float4*)embw)[(size_t)id * 64 + h4];
    ((float4*)xv)[(size_t)bs * 64 + h4] = vv;
    float4 dv = make_float4(0.f, 0.f, 0.f, 0.f);
    if (id > 0) dv = ((const float4*)dag)[(size_t)(id - 1) * 64 + h4];
    ((float4*)xd)[(size_t)bs * 64 + h4] = dv;

    uint32_t h0, l0, h1, l1;
    split2(vv.x, vv.y, h0, l0);
    split2(vv.z, vv.w, h1, l1);
    xvh[(size_t)bs * 128 + h4 * 2]     = h0;
    xvh[(size_t)bs * 128 + h4 * 2 + 1] = h1;
    xvl[(size_t)bs * 128 + h4 * 2]     = l0;
    xvl[(size_t)bs * 128 + h4 * 2 + 1] = l1;
    split2(dv.x, dv.y, h0, l0);
    split2(dv.z, dv.w, h1, l1);
    xdh[(size_t)bs * 128 + h4 * 2]     = h0;
    xdh[(size_t)bs * 128 + h4 * 2 + 1] = h1;
    xdl[(size_t)bs * 128 + h4 * 2]     = l0;
    xdl[(size_t)bs * 128 + h4 * 2 + 1] = l1;
}

// ---------------- attention: SIMT chunked online softmax (z selects) ----------
struct A2 {
    const float *qkv0, *qkv1;
    uint32_t *h0, *l0, *h1, *l1;
};

__global__ void attention_kernel(A2 g, const float* __restrict__ cmask)
{
    extern __shared__ float sm[];
    float* Ks = sm;
    float* Vs = sm + S * Dh;
    float* madd = Vs + S * Dh;
    const int h = blockIdx.x, b = blockIdx.y, z = blockIdx.z;
    const float* __restrict__ QKV = z ? g.qkv1 : g.qkv0;
    uint32_t* __restrict__ cth = z ? g.h1 : g.h0;
    uint32_t* __restrict__ ctl = z ? g.l1 : g.l0;
    const int tid = threadIdx.x;
    const size_t rowbase = (size_t)b * S * QKVN;
    const int qo = h * Dh, ko = H + h * Dh, vo = 2 * H + h * Dh;

    for (int i = tid; i < S * 8; i += 256) {
        int row = i >> 3, slot = (i & 7) << 2;
        *(float4*)&Ks[row * Dh + slot] = *(const float4*)&QKV[rowbase + (size_t)row * QKVN + ko + slot];
        *(float4*)&Vs[row * Dh + slot] = *(const float4*)&QKV[rowbase + (size_t)row * QKVN + vo + slot];
    }
    madd[tid] = (1.0f - cmask[b * S + tid]) * VERY_NEG;
    __syncthreads();

    float q[32];
    const float* qp = &QKV[rowbase + (size_t)tid * QKVN + qo];
    #pragma unroll
    for (int i = 0; i < 32; i += 4) {
        float4 t = *(const float4*)&qp[i];
        q[i] = t.x; q[i + 1] = t.y; q[i + 2] = t.z; q[i + 3] = t.w;
    }
    const float scale = rsqrtf(32.0f);
    float m = -INFINITY, l = 0.f, o[32];
    #pragma unroll
    for (int i = 0; i < 32; i++) o[i] = 0.f;

    for (int k0 = 0; k0 < S; k0 += 16) {
        float sc[16];
        float cm = -INFINITY;
        #pragma unroll
        for (int kk = 0; kk < 16; kk++) {
            const float* kr = &Ks[(k0 + kk) * Dh];
            float d = 0.f;
            #pragma unroll
            for (int i = 0; i < 32; i++) d = fmaf(q[i], kr[i], d);
            sc[kk] = d * scale + madd[k0 + kk];
            cm = fmaxf(cm, sc[kk]);
        }
        const float mn = fmaxf(m, cm);
        const float corr = __expf(m - mn);
        l *= corr;
        #pragma unroll
        for (int i = 0; i < 32; i++) o[i] *= corr;
        #pragma unroll
        for (int kk = 0; kk < 16; kk++) {
            const float p = __expf(sc[kk] - mn);
            l += p;
            const float* vr = &Vs[(k0 + kk) * Dh];
            #pragma unroll
            for (int i = 0; i < 32; i++) o[i] = fmaf(p, vr[i], o[i]);
        }
        m = mn;
    }
    const float inv = 1.0f / l;
    const size_t prow = (size_t)(b * S + tid) * 128 + h * 16;
    #pragma unroll
    for (int i = 0; i < 32; i += 2) {
        uint32_t hw, lw;
        split2(o[i] * inv, o[i + 1] * inv, hw, lw);
        cth[prow + i / 2] = hw;
        ctl[prow + i / 2] = lw;
    }
}

// ---------------- pooling ------------------------------------------------------
__global__ void pool_kernel(const float* __restrict__ x, const float* __restrict__ cmask,
                            const float* __restrict__ pw, const float* __restrict__ pb,
                            float* __restrict__ out)
{
    __shared__ float spw[H];
    __shared__ float sc[S];
    __shared__ float red[8];
    const int b = blockIdx.x, tid = threadIdx.x;
    const int lane = tid & 31, w = tid >> 5;
    spw[tid] = pw[tid];
    __syncthreads();

    for (int row = w; row < S; row += 8) {
        const float* xp = &x[((size_t)b * S + row) * H];
        float4 a0 = *(const float4*)&xp[lane * 4];
        float4 a1 = *(const float4*)&xp[128 + lane * 4];
        float acc = a0.x * spw[lane * 4 + 0] + a0.y * spw[lane * 4 + 1]
                  + a0.z * spw[lane * 4 + 2] + a0.w * spw[lane * 4 + 3]
                  + a1.x * spw[128 + lane * 4 + 0] + a1.y * spw[128 + lane * 4 + 1]
                  + a1.z * spw[128 + lane * 4 + 2] + a1.w * spw[128 + lane * 4 + 3];
        #pragma unroll
        for (int off = 16; off; off >>= 1) acc += __shfl_xor_sync(0xffffffffu, acc, off);
        if (lane == 0)
            sc[row] = acc + pb[0] + (1.f - cmask[b * S + row]) * VERY_NEG;
    }
    __syncthreads();

    float v = sc[tid];
    float mx = v;
    #pragma unroll
    for (int off = 16; off; off >>= 1) mx = fmaxf(mx, __shfl_xor_sync(0xffffffffu, mx, off));
    if (lane == 0) red[w] = mx;
    __syncthreads();
    float bm = red[0];
    #pragma unroll
    for (int i = 1; i < 8; i++) bm = fmaxf(bm, red[i]);
    __syncthreads();
    float e = __expf(v - bm);
    float su = e;
    #pragma unroll
    for (int off = 16; off; off >>= 1) su += __shfl_xor_sync(0xffffffffu, su, off);
    if (lane == 0) red[w] = su;
    __syncthreads();
    float tot = 0.f;
    #pragma unroll
    for (int i = 0; i < 8; i++) tot += red[i];
    sc[tid] = e / tot;
    __syncthreads();

    float acc = 0.f;
    for (int ss = 0; ss < S; ss++)
        acc = fmaf(sc[ss], x[((size_t)b * S + ss) * H + tid], acc);
    out[(size_t)b * H + tid] = acc;
}

// ---------------- host ----------------------------------------------------------
extern "C" void kernel_launch(void* const* d_in, const int* in_sizes, int n_in,
                              void* d_out, int out_size)
{
    const int*   input_ids   = (const int*)d_in[0];
    const float* code_mask   = (const float*)d_in[1];
    const int*   dx_leaves   = (const int*)d_in[2];
    const int*   dx_anc      = (const int*)d_in[3];
    const float* dx_mask     = (const float*)d_in[4];
    const float* embed_init  = (const float*)d_in[5];
    const float* embed_inp   = (const float*)d_in[6];
    const float* attn_w1     = (const float*)d_in[7];
    const float* attn_b1     = (const float*)d_in[8];
    const float* attn_w2     = (const float*)d_in[9];
    const float* attn_b2     = (const float*)d_in[10];
    const float* pool_w      = (const float*)d_in[11];
    const float* pool_b      = (const float*)d_in[12];
    const float* enc_w[2][8];
    for (int z = 0; z < 2; z++)
        for (int j = 0; j < 8; j++)
            enc_w[z][j] = (const float*)d_in[13 + z * 8 + j];
    float* out = (float*)d_out;

    uint32_t *eh, *el, *xvh, *xvl, *xdh, *xdl, *w1h, *w1l;
    uint32_t *cth[2], *ctl[2], *th[2], *tl[2], *fh[2], *fl[2];
    uint32_t *wqkvh[2], *wqkvl[2], *woh[2], *wol[2], *f1h[2], *f1l[2], *f2h[2], *f2l[2];
    float *s, *dag, *xv, *xd, *xdo, *qkv[2], *t[2];
    {
        char* p;
        cudaGetSymbolAddress((void**)&eh, g_eh);   cudaGetSymbolAddress((void**)&el, g_el);
        cudaGetSymbolAddress((void**)&s, g_s);     cudaGetSymbolAddress((void**)&dag, g_dag);
        cudaGetSymbolAddress((void**)&xv, g_xv);   cudaGetSymbolAddress((void**)&xd, g_xd);
        cudaGetSymbolAddress((void**)&xvh, g_xvh); cudaGetSymbolAddress((void**)&xvl, g_xvl);
        cudaGetSymbolAddress((void**)&xdh, g_xdh); cudaGetSymbolAddress((void**)&xdl, g_xdl);
        cudaGetSymbolAddress((void**)&xdo, g_xdo);
        cudaGetSymbolAddress((void**)&w1h, g_w1h); cudaGetSymbolAddress((void**)&w1l, g_w1l);
        cudaGetSymbolAddress((void**)&p, g_qkv);   qkv[0] = (float*)p;    qkv[1] = qkv[0] + (size_t)BS * QKVN;
        cudaGetSymbolAddress((void**)&p, g_t);     t[0] = (float*)p;      t[1] = t[0] + (size_t)BS * H;
        cudaGetSymbolAddress((void**)&p, g_cth);   cth[0] = (uint32_t*)p; cth[1] = cth[0] + (size_t)BS * 128;
        cudaGetSymbolAddress((void**)&p, g_ctl);   ctl[0] = (uint32_t*)p; ctl[1] = ctl[0] + (size_t)BS * 128;
        cudaGetSymbolAddress((void**)&p, g_th);    th[0] = (uint32_t*)p;  th[1] = th[0] + (size_t)BS * 128;
        cudaGetSymbolAddress((void**)&p, g_tl);    tl[0] = (uint32_t*)p;  tl[1] = tl[0] + (size_t)BS * 128;
        cudaGetSymbolAddress((void**)&p, g_fh);    fh[0] = (uint32_t*)p;  fh[1] = fh[0] + (size_t)BS * 512;
        cudaGetSymbolAddress((void**)&p, g_fl);    fl[0] = (uint32_t*)p;  fl[1] = fl[0] + (size_t)BS * 512;
        cudaGetSymbolAddress((void**)&p, g_wqkvh); wqkvh[0] = (uint32_t*)p; wqkvh[1] = wqkvh[0] + 128 * QKVN;
        cudaGetSymbolAddress((void**)&p, g_wqkvl); wqkvl[0] = (uint32_t*)p; wqkvl[1] = wqkvl[0] + 128 * QKVN;
        cudaGetSymbolAddress((void**)&p, g_woh);   woh[0] = (uint32_t*)p;   woh[1] = woh[0] + 128 * 256;
        cudaGetSymbolAddress((void**)&p, g_wol);   wol[0] = (uint32_t*)p;   wol[1] = wol[0] + 128 * 256;
        cudaGetSymbolAddress((void**)&p, g_f1h);   f1h[0] = (uint32_t*)p;   f1h[1] = f1h[0] + 128 * 1024;
        cudaGetSymbolAddress((void**)&p, g_f1l);   f1l[0] = (uint32_t*)p;   f1l[1] = f1l[0] + 128 * 1024;
        cudaGetSymbolAddress((void**)&p, g_f2h);   f2h[0] = (uint32_t*)p;   f2h[1] = f2h[0] + 512 * 256;
        cudaGetSymbolAddress((void**)&p, g_f2l);   f2l[0] = (uint32_t*)p;   f2l[1] = f2l[0] + 512 * 256;
    }

    const int asmem = (2 * S * Dh + S) * (int)sizeof(float);
    cudaFuncSetAttribute(attention_kernel, cudaFuncAttributeMaxDynamicSharedMemorySize, asmem);
    cudaFuncSetAttribute(tgemm_kernel<true, true, false, true, false, false, true>,
                         cudaFuncAttributeMaxDynamicSharedMemorySize, GSM);
    cudaFuncSetAttribute(tgemm_kernel<false, false, false, false, true, false, false>,
                         cudaFuncAttributeMaxDynamicSharedMemorySize, GSM);
    cudaFuncSetAttribute(tgemm_kernel<false, false, true, false, true, true, false>,
                         cudaFuncAttributeMaxDynamicSharedMemorySize, GSM);
    cudaFuncSetAttribute(tgemm_kernel<true, true, false, false, false, true, false>,
                         cudaFuncAttributeMaxDynamicSharedMemorySize, GSM);
    cudaFuncSetAttribute(tgemm_kernel<false, true, true, false, true, false, false>,
                         cudaFuncAttributeMaxDynamicSharedMemorySize, GSM);

    const int PT = 256;
    pack_contig_kernel<<<(NODES1 * 128 + PT - 1) / PT, PT>>>(embed_init, eh, el, NODES1 * 128);
    s_init_kernel<<<(CA + PT - 1) / PT, PT>>>(s, attn_b2);

    // merged weight packing
    {
        PackAll pa{};
        int cur = 0, si = 0;
        auto add = [&](const float* src, uint32_t* dh, uint32_t* dl,
                       int Khalf, int Nsrc, int Ndst, int coff) {
            pa.seg[si] = {src, dh, dl, Khalf, Nsrc, Ndst, coff, cur};
            cur += Khalf * Nsrc;
            si++;
        };
        add(attn_w1, w1h, w1l, 256, 256, 256, 0);
        for (int z = 0; z < 2; z++) {
            add(enc_w[z][0], wqkvh[z], wqkvl[z], 128, 256, QKVN, 0);
            add(enc_w[z][1], wqkvh[z], wqkvl[z], 128, 256, QKVN, 256);
            add(enc_w[z][2], wqkvh[z], wqkvl[z], 128, 256, QKVN, 512);
            add(enc_w[z][3], woh[z], wol[z], 128, 256, 256, 0);
            add(enc_w[z][4], f1h[z], f1l[z], 128, 1024, 1024, 0);
            add(enc_w[z][6], f2h[z], f2l[z], 512, 256, 256, 0);
        }
        pa.total = cur;
        pack_all_kernel<<<(cur + PT - 1) / PT, PT>>>(pa);
    }

    // DAG MLP: gathered A + fused score
    {
        G2 g{};
        g.Ah0 = g.Ah1 = eh;  g.Al0 = g.Al1 = el;
        g.Bh0 = g.Bh1 = w1h; g.Bl0 = g.Bl1 = w1l;
        g.bias0 = g.bias1 = attn_b1;
        tgemm_kernel<true, true, false, true, false, false, true><<<dim3(2, CA / 128, 1), 256, GSM>>>(
            g, attn_w2, s, CA, 256, 512, dx_leaves, dx_anc);
    }
    dag_softmax_kernel<<<C / 8, 256>>>(s, dx_mask, dx_anc, embed_init, dag);
    embed_gather_kernel<<<(BS * 64 + PT - 1) / PT, PT>>>(input_ids, embed_inp, dag,
                                                         xv, xd, xvh, xvl, xdh, xdl);

    // --- both encoders batched over gridDim.z ---
    {
        G2 g{};
        g.Ah0 = xvh; g.Al0 = xvl; g.Ah1 = xdh; g.Al1 = xdl;
        g.Bh0 = wqkvh[0]; g.Bl0 = wqkvl[0]; g.Bh1 = wqkvh[1]; g.Bl1 = wqkvl[1];
        g.Cm0 = qkv[0]; g.Cm1 = qkv[1];
        tgemm_kernel<false, false, false, false, true, false, false><<<dim3(QKVN / 128, BS / 128, 2), 256, GSM>>>(
            g, nullptr, nullptr, BS, QKVN, H, nullptr, nullptr);
    }
    {
        A2 a{qkv[0], qkv[1], cth[0], ctl[0], cth[1], ctl[1]};
        attention_kernel<<<dim3(NH, Bz, 2), 256, asmem>>>(a, code_mask);
    }
    {
        G2 g{};
        g.Ah0 = cth[0]; g.Al0 = ctl[0]; g.Ah1 = cth[1]; g.Al1 = ctl[1];
        g.Bh0 = woh[0]; g.Bl0 = wol[0]; g.Bh1 = woh[1]; g.Bl1 = wol[1];
        g.Res0 = xv; g.Res1 = xd;
        g.Cm0 = t[0]; g.Cm1 = t[1];
        g.Ch0 = th[0]; g.Cl0 = tl[0]; g.Ch1 = th[1]; g.Cl1 = tl[1];
        tgemm_kernel<false, false, true, false, true, true, false><<<dim3(2, BS / 128, 2), 256, GSM>>>(
            g, nullptr, nullptr, BS, H, H, nullptr, nullptr);
    }
    {
        G2 g{};
        g.Ah0 = th[0]; g.Al0 = tl[0]; g.Ah1 = th[1]; g.Al1 = tl[1];
        g.Bh0 = f1h[0]; g.Bl0 = f1l[0]; g.Bh1 = f1h[1]; g.Bl1 = f1l[1];
        g.bias0 = enc_w[0][5]; g.bias1 = enc_w[1][5];
        g.Ch0 = fh[0]; g.Cl0 = fl[0]; g.Ch1 = fh[1]; g.Cl1 = fl[1];
        tgemm_kernel<true, true, false, false, false, true, false><<<dim3(FF / 128, BS / 128, 2), 256, GSM>>>(
            g, nullptr, nullptr, BS, FF, H, nullptr, nullptr);
    }
    {
        G2 g{};
        g.Ah0 = fh[0]; g.Al0 = fl[0]; g.Ah1 = fh[1]; g.Al1 = fl[1];
        g.Bh0 = f2h[0]; g.Bl0 = f2l[0]; g.Bh1 = f2h[1]; g.Bl1 = f2l[1];
        g.bias0 = enc_w[0][7]; g.bias1 = enc_w[1][7];
        g.Res0 = t[0]; g.Res1 = t[1];
        g.Cm0 = out; g.Cm1 = xdo;
        tgemm_kernel<false, true, true, false, true, false, false><<<dim3(2, BS / 128, 2), 256, GSM>>>(
            g, nullptr, nullptr, BS, H, FF, nullptr, nullptr);
    }

    pool_kernel<<<Bz, 256>>>(xdo, code_mask, pool_w, pool_b, out + (size_t)BS * H);
}

// round 15
// speedup vs baseline: 1.7301x; 1.2780x over previous
#include <cuda_runtime.h>
#include <cuda_bf16.h>
#include <math.h>
#include <stdint.h>

#define VERY_NEG (-1e30f)

constexpr int Bz = 128;
constexpr int S  = 256;
constexpr int H  = 256;
constexpr int NH = 8;
constexpr int Dh = 32;
constexpr int C  = 20000;
constexpr int A  = 8;
constexpr int BS = Bz * S;
constexpr int CA = C * A;
constexpr int FF = 4 * H;
constexpr int NODES1 = 25001;
constexpr int QKVN = 3 * H;

// dynamic smem: 3 stages x (A 128x12 + B 8x136) x {h,l}
constexpr int AW = 128 * 12;
constexpr int BW = 8 * 136;
constexpr int GSM = 3 * (AW + BW) * 2 * 4;

// ---------------- scratch ------------------------------------------------------
__device__ uint32_t g_eh [(size_t)NODES1 * 128];
__device__ uint32_t g_el [(size_t)NODES1 * 128];
__device__ float    g_s  [CA];
__device__ float    g_dag[(size_t)C * H];
__device__ float    g_xv [(size_t)BS * H];
__device__ float    g_xd [(size_t)BS * H];
__device__ uint32_t g_xvh[(size_t)BS * 128], g_xvl[(size_t)BS * 128];
__device__ uint32_t g_xdh[(size_t)BS * 128], g_xdl[(size_t)BS * 128];
__device__ float    g_qkv[2][(size_t)BS * QKVN];
__device__ uint32_t g_cth[2][(size_t)BS * 128], g_ctl[2][(size_t)BS * 128];
__device__ float    g_t  [2][(size_t)BS * H];
__device__ uint32_t g_th [2][(size_t)BS * 128], g_tl [2][(size_t)BS * 128];
__device__ uint32_t g_fh [2][(size_t)BS * 512], g_fl [2][(size_t)BS * 512];
__device__ float    g_xdo[(size_t)BS * H];
__device__ uint32_t g_wqkvh[2][128 * QKVN], g_wqkvl[2][128 * QKVN];
__device__ uint32_t g_woh [2][128 * 256],  g_wol [2][128 * 256];
__device__ uint32_t g_f1h [2][128 * 1024], g_f1l [2][128 * 1024];
__device__ uint32_t g_f2h [2][512 * 256],  g_f2l [2][512 * 256];
__device__ uint32_t g_w1h [256 * 256],  g_w1l [256 * 256];

// ---------------- helpers ------------------------------------------------------
__device__ __forceinline__ void mma_bf16(float* c, const uint32_t* a, const uint32_t* b) {
    asm volatile(
        "mma.sync.aligned.m16n8k16.row.col.f32.bf16.bf16.f32 "
        "{%0,%1,%2,%3}, {%4,%5,%6,%7}, {%8,%9}, {%0,%1,%2,%3};\n"
        : "+f"(c[0]), "+f"(c[1]), "+f"(c[2]), "+f"(c[3])
        : "r"(a[0]), "r"(a[1]), "r"(a[2]), "r"(a[3]),
          "r"(b[0]), "r"(b[1]));
}

__device__ __forceinline__ void split2(float x0, float x1, uint32_t& hi, uint32_t& lo) {
    __nv_bfloat16 h0 = __float2bfloat16_rn(x0);
    __nv_bfloat16 h1 = __float2bfloat16_rn(x1);
    __nv_bfloat16 l0 = __float2bfloat16_rn(x0 - __bfloat162float(h0));
    __nv_bfloat16 l1 = __float2bfloat16_rn(x1 - __bfloat162float(h1));
    hi = ((uint32_t)__bfloat16_as_ushort(h1) << 16) | __bfloat16_as_ushort(h0);
    lo = ((uint32_t)__bfloat16_as_ushort(l1) << 16) | __bfloat16_as_ushort(l0);
}

__device__ __forceinline__ uint32_t packbf(float a, float b) {
    __nv_bfloat162 t = __floats2bfloat162_rn(a, b);
    return *reinterpret_cast<uint32_t*>(&t);
}

#define CP_ASYNC16(dst, src) \
    asm volatile("cp.async.cg.shared.global [%0], [%1], 16;" :: "r"(dst), "l"(src) : "memory")
#define CP_COMMIT()  asm volatile("cp.async.commit_group;" ::: "memory")
#define CP_WAIT0()   asm volatile("cp.async.wait_group 0;" ::: "memory")
#define CP_WAIT1()   asm volatile("cp.async.wait_group 1;" ::: "memory")

__global__ void pack_contig_kernel(const float* __restrict__ src, uint32_t* __restrict__ dh,
                                   uint32_t* __restrict__ dl, int n2)
{
    int idx = blockIdx.x * blockDim.x + threadIdx.x;
    if (idx >= n2) return;
    float2 v = ((const float2*)src)[idx];
    uint32_t h, l;
    split2(v.x, v.y, h, l);
    dh[idx] = h; dl[idx] = l;
}

struct PackSeg {
    const float* src;
    uint32_t *dh, *dl;
    int Khalf, Nsrc, Ndst, coff, start;
};
struct PackAll { PackSeg seg[13]; int total; };

__global__ void pack_all_kernel(PackAll pa)
{
    int idx = blockIdx.x * blockDim.x + threadIdx.x;
    if (idx >= pa.total) return;
    int si = 0;
    #pragma unroll
    for (int i = 1; i < 13; i++)
        if (idx >= pa.seg[i].start) si = i;
    const PackSeg& sg = pa.seg[si];
    int li = idx - sg.start;
    int kp = li / sg.Nsrc, n = li - kp * sg.Nsrc;
    float a = sg.src[(size_t)(2 * kp) * sg.Nsrc + n];
    float b = sg.src[(size_t)(2 * kp + 1) * sg.Nsrc + n];
    uint32_t h, l;
    split2(a, b, h, l);
    sg.dh[(size_t)kp * sg.Ndst + sg.coff + n] = h;
    sg.dl[(size_t)kp * sg.Ndst + sg.coff + n] = l;
}

__global__ void s_init_kernel(float* __restrict__ s, const float* __restrict__ b2)
{
    int idx = blockIdx.x * blockDim.x + threadIdx.x;
    if (idx < CA) s[idx] = b2[0];
}

// ---------------- pointer-pair arg block (z selects encoder) -------------------
struct G2 {
    const uint32_t *Ah0, *Al0, *Bh0, *Bl0;
    const uint32_t *Ah1, *Al1, *Bh1, *Bl1;
    const float *bias0, *bias1, *Res0, *Res1;
    float *Cm0, *Cm1;
    uint32_t *Ch0, *Cl0, *Ch1, *Cl1;
};

// ---------------- split-bf16 tensor GEMM: 3-stage cp.async pipeline -----------
template <bool RELU, bool BIAS, bool RES, bool GATHER, bool OUTF32, bool SPLIT, bool SCORE>
__global__ __launch_bounds__(256, 2)
void tgemm_kernel(G2 g, const float* __restrict__ w2, float* __restrict__ sout,
                  int M, int N, int K,
                  const int* __restrict__ gl, const int* __restrict__ ga)
{
    extern __shared__ uint32_t dsm[];
    uint32_t* ASH = dsm;
    uint32_t* ASL = dsm + 3 * AW;
    uint32_t* BSH = dsm + 6 * AW;
    uint32_t* BSL = dsm + 6 * AW + 3 * BW;

    const int z = blockIdx.z;
    const uint32_t* __restrict__ Ah = z ? g.Ah1 : g.Ah0;
    const uint32_t* __restrict__ Al = z ? g.Al1 : g.Al0;
    const uint32_t* __restrict__ Bh = z ? g.Bh1 : g.Bh0;
    const uint32_t* __restrict__ Bl = z ? g.Bl1 : g.Bl0;
    const float* __restrict__ bias  = z ? g.bias1 : g.bias0;
    const float* __restrict__ Res   = z ? g.Res1 : g.Res0;
    float* __restrict__ Cm          = z ? g.Cm1 : g.Cm0;
    uint32_t* __restrict__ Ch       = z ? g.Ch1 : g.Ch0;
    uint32_t* __restrict__ Cl       = z ? g.Cl1 : g.Cl0;

    const int tid  = threadIdx.x;
    const int lane = tid & 31;
    const int wid  = tid >> 5;
    const int warp_m = wid & 3;
    const int warp_n = wid >> 2;
    const int m0 = blockIdx.y * 128, n0 = blockIdx.x * 128;
    const int r = lane >> 2, c = lane & 3;
    const int Khalf = K >> 1;

    const int arow   = tid >> 1;
    const int ahalf4 = (tid & 1) << 2;
    const int bkp    = tid >> 5;
    const int bcol4  = (tid & 31) << 2;

    int grow_l = 0, grow_a = 0;
    if (GATHER) {
        grow_l = gl[m0 + arow];
        grow_a = ga[m0 + arow];
    }

    uint32_t a_h_dst = (uint32_t)__cvta_generic_to_shared(&ASH[arow * 12 + ahalf4]);
    uint32_t a_l_dst = (uint32_t)__cvta_generic_to_shared(&ASL[arow * 12 + ahalf4]);
    uint32_t b_h_dst = (uint32_t)__cvta_generic_to_shared(&BSH[bkp * 136 + bcol4]);
    uint32_t b_l_dst = (uint32_t)__cvta_generic_to_shared(&BSL[bkp * 136 + bcol4]);

    float acc[2][8][4] = {};

    auto issue_tile = [&](int buf, int k0) {
        const int kpb = k0 >> 1;
        size_t aaddr;
        if (GATHER) {
            const int kglob = k0 + ahalf4 * 2;
            const int src = (kglob < 256) ? grow_l : grow_a;
            aaddr = (size_t)src * 128 + ((kpb + ahalf4) & 127);
        } else {
            aaddr = (size_t)(m0 + arow) * Khalf + kpb + ahalf4;
        }
        CP_ASYNC16(a_h_dst + buf * (AW * 4), &Ah[aaddr]);
        CP_ASYNC16(a_l_dst + buf * (AW * 4), &Al[aaddr]);
        const size_t baddr = (size_t)(kpb + bkp) * N + n0 + bcol4;
        CP_ASYNC16(b_h_dst + buf * (BW * 4), &Bh[baddr]);
        CP_ASYNC16(b_l_dst + buf * (BW * 4), &Bl[baddr]);
    };

    const int ntiles = K >> 4;
    issue_tile(0, 0);
    CP_COMMIT();
    if (ntiles > 1) { issue_tile(1, 16); CP_COMMIT(); }

    int cur = 0;
    for (int t = 0; t < ntiles; t++) {
        if (t + 1 < ntiles) CP_WAIT1(); else CP_WAIT0();
        __syncthreads();

        uint32_t a_h[2][4], a_l[2][4], b_h[8][2], b_l[8][2];
        const uint32_t* Ahc = ASH + cur * AW;
        const uint32_t* Alc = ASL + cur * AW;
        const uint32_t* Bhc = BSH + cur * BW;
        const uint32_t* Blc = BSL + cur * BW;
        #pragma unroll
        for (int mt = 0; mt < 2; mt++) {
            const int row = warp_m * 32 + mt * 16 + r;
            a_h[mt][0] = Ahc[row * 12 + c];
            a_h[mt][1] = Ahc[(row + 8) * 12 + c];
            a_h[mt][2] = Ahc[row * 12 + c + 4];
            a_h[mt][3] = Ahc[(row + 8) * 12 + c + 4];
            a_l[mt][0] = Alc[row * 12 + c];
            a_l[mt][1] = Alc[(row + 8) * 12 + c];
            a_l[mt][2] = Alc[row * 12 + c + 4];
            a_l[mt][3] = Alc[(row + 8) * 12 + c + 4];
        }
        #pragma unroll
        for (int nt = 0; nt < 8; nt++) {
            const int col = warp_n * 64 + nt * 8 + r;
            b_h[nt][0] = Bhc[c * 136 + col];
            b_h[nt][1] = Bhc[(c + 4) * 136 + col];
            b_l[nt][0] = Blc[c * 136 + col];
            b_l[nt][1] = Blc[(c + 4) * 136 + col];
        }

        if (t + 2 < ntiles) {
            int nxt = cur + 2;
            if (nxt >= 3) nxt -= 3;
            issue_tile(nxt, (t + 2) << 4);
            CP_COMMIT();
        }

        #pragma unroll
        for (int mt = 0; mt < 2; mt++)
            #pragma unroll
            for (int nt = 0; nt < 8; nt++) {
                mma_bf16(acc[mt][nt], a_h[mt], b_h[nt]);
                mma_bf16(acc[mt][nt], a_h[mt], b_l[nt]);
                mma_bf16(acc[mt][nt], a_l[mt], b_h[nt]);
            }

        cur = (cur == 2) ? 0 : cur + 1;
    }

    float partial[4] = {0.f, 0.f, 0.f, 0.f};

    #pragma unroll
    for (int mt = 0; mt < 2; mt++) {
        #pragma unroll
        for (int nt = 0; nt < 8; nt++) {
            const int row0 = m0 + warp_m * 32 + mt * 16 + r;
            const int col  = n0 + warp_n * 64 + nt * 8 + 2 * c;
            #pragma unroll
            for (int h = 0; h < 2; h++) {
                float2 v = make_float2(acc[mt][nt][h * 2], acc[mt][nt][h * 2 + 1]);
                if (BIAS) {
                    const float2 bb = *(const float2*)&bias[col];
                    v.x += bb.x; v.y += bb.y;
                }
                if (RELU) { v.x = fmaxf(v.x, 0.f); v.y = fmaxf(v.y, 0.f); }
                const int row = row0 + h * 8;
                const size_t off = (size_t)row * N + col;
                if (RES) {
                    const float2 rr = *(const float2*)&Res[off];
                    v.x += rr.x; v.y += rr.y;
                }
                if (SCORE) {
                    const float2 ww = *(const float2*)&w2[col];
                    partial[mt * 2 + h] += v.x * ww.x + v.y * ww.y;
                }
                if (OUTF32) *(float2*)&Cm[off] = v;
                if (SPLIT) {
                    uint32_t hw, lw;
                    split2(v.x, v.y, hw, lw);
                    Ch[(size_t)row * (N >> 1) + (col >> 1)] = hw;
                    Cl[(size_t)row * (N >> 1) + (col >> 1)] = lw;
                }
            }
        }
    }

    if (SCORE) {
        #pragma unroll
        for (int mt = 0; mt < 2; mt++)
            #pragma unroll
            for (int h = 0; h < 2; h++) {
                float p = partial[mt * 2 + h];
                p += __shfl_xor_sync(0xffffffffu, p, 1);
                p += __shfl_xor_sync(0xffffffffu, p, 2);
                if ((lane & 3) == 0) {
                    const int row = m0 + warp_m * 32 + mt * 16 + r + h * 8;
                    atomicAdd(&sout[row], p);
                }
            }
    }
}

// ---------------- DAG softmax + weighted ancestor sum --------------------------
__global__ void dag_softmax_kernel(const float* __restrict__ s, const float* __restrict__ mask,
                                   const int* __restrict__ anc, const float* __restrict__ emb,
                                   float* __restrict__ dag)
{
    int gw = (blockIdx.x * blockDim.x + threadIdx.x) >> 5;
    int lane = threadIdx.x & 31;
    if (gw >= C) return;
    float sv = -3.0e38f;
    int av = 0;
    if (lane < 8) {
        float m = mask[gw * 8 + lane];
        sv = s[gw * 8 + lane] + (1.f - m) * VERY_NEG;
        av = anc[gw * 8 + lane];
    }
    float mx = sv;
    #pragma unroll
    for (int off = 4; off; off >>= 1) mx = fmaxf(mx, __shfl_xor_sync(0xffffffffu, mx, off));
    float e = (lane < 8) ? __expf(sv - mx) : 0.f;
    float su = e;
    #pragma unroll
    for (int off = 4; off; off >>= 1) su += __shfl_xor_sync(0xffffffffu, su, off);
    float wv = e / su;
    float w8[8];
    int   a8[8];
    #pragma unroll
    for (int a = 0; a < 8; a++) {
        w8[a] = __shfl_sync(0xffffffffu, wv, a);
        a8[a] = __shfl_sync(0xffffffffu, av, a);
    }
    const float4* e4 = (const float4*)emb;
    #pragma unroll
    for (int rep = 0; rep < 2; rep++) {
        int f4i = lane + rep * 32;
        float4 acc = make_float4(0.f, 0.f, 0.f, 0.f);
        #pragma unroll
        for (int a = 0; a < 8; a++) {
            float4 v = e4[(size_t)a8[a] * 64 + f4i];
            acc.x = fmaf(w8[a], v.x, acc.x);
            acc.y = fmaf(w8[a], v.y, acc.y);
            acc.z = fmaf(w8[a], v.z, acc.z);
            acc.w = fmaf(w8[a], v.w, acc.w);
        }
        ((float4*)dag)[(size_t)gw * 64 + f4i] = acc;
    }
}

__global__ void embed_gather_kernel(const int* __restrict__ ids, const float* __restrict__ embw,
                                    const float* __restrict__ dag,
                                    float* __restrict__ xv, float* __restrict__ xd,
                                    uint32_t* __restrict__ xvh, uint32_t* __restrict__ xvl,
                                    uint32_t* __restrict__ xdh, uint32_t* __restrict__ xdl)
{
    int idx = blockIdx.x * blockDim.x + threadIdx.x;
    if (idx >= BS * 64) return;
    int bs = idx >> 6, h4 = idx & 63;
    int id = ids[bs];
    float4 vv = ((const float4*)embw)[(size_t)id * 64 + h4];
    ((float4*)xv)[(size_t)bs * 64 + h4] = vv;
    float4 dv = make_float4(0.f, 0.f, 0.f, 0.f);
    if (id > 0) dv = ((const float4*)dag)[(size_t)(id - 1) * 64 + h4];
    ((float4*)xd)[(size_t)bs * 64 + h4] = dv;

    uint32_t h0, l0, h1, l1;
    split2(vv.x, vv.y, h0, l0);
    split2(vv.z, vv.w, h1, l1);
    xvh[(size_t)bs * 128 + h4 * 2]     = h0;
    xvh[(size_t)bs * 128 + h4 * 2 + 1] = h1;
    xvl[(size_t)bs * 128 + h4 * 2]     = l0;
    xvl[(size_t)bs * 128 + h4 * 2 + 1] = l1;
    split2(dv.x, dv.y, h0, l0);
    split2(dv.z, dv.w, h1, l1);
    xdh[(size_t)bs * 128 + h4 * 2]     = h0;
    xdh[(size_t)bs * 128 + h4 * 2 + 1] = h1;
    xdl[(size_t)bs * 128 + h4 * 2]     = l0;
    xdl[(size_t)bs * 128 + h4 * 2 + 1] = l1;
}

// ---------------- MMA flash attention, 16 q/warp, 32-key chunks ----------------
struct A2 {
    const float *qkv0, *qkv1;
    uint32_t *h0, *l0, *h1, *l1;
};

__global__ __launch_bounds__(256)
void attention_kernel(A2 g, const float* __restrict__ cmask)
{
    __shared__ float    madd[S];
    __shared__ uint32_t Ksh[16 * 40], Ksl[16 * 40];   // [dh_pair][key(32)+pad]
    __shared__ uint32_t Vsh[16 * 40], Vsl[16 * 40];   // [key_pair][dh(32)+pad]

    const int h = blockIdx.x, b = blockIdx.y, z = blockIdx.z;
    const int enc = z & 1, qh2 = z >> 1;
    const float* __restrict__ QKV = enc ? g.qkv1 : g.qkv0;
    uint32_t* __restrict__ cth = enc ? g.h1 : g.h0;
    uint32_t* __restrict__ ctl = enc ? g.l1 : g.l0;
    const int tid = threadIdx.x, w = tid >> 5, lane = tid & 31;
    const int gg = lane >> 2, t = lane & 3;
    const size_t rowbase = (size_t)b * S * QKVN;
    const int qo = h * Dh, ko = H + h * Dh, vo = 2 * H + h * Dh;
    const float scale = rsqrtf(32.0f);

    madd[tid] = (1.0f - cmask[b * S + tid]) * VERY_NEG;

    // Q fragments: 16 queries per warp, scale folded before split
    const int rA = qh2 * 128 + w * 16 + gg, rB = rA + 8;
    uint32_t qh[2][4], ql[2][4];
    {
        const float* qA = &QKV[rowbase + (size_t)rA * QKVN + qo];
        const float* qB = &QKV[rowbase + (size_t)rB * QKVN + qo];
        #pragma unroll
        for (int kc = 0; kc < 2; kc++) {
            float2 v0 = *(const float2*)&qA[16 * kc + 2 * t];
            float2 v1 = *(const float2*)&qB[16 * kc + 2 * t];
            float2 v2 = *(const float2*)&qA[16 * kc + 2 * t + 8];
            float2 v3 = *(const float2*)&qB[16 * kc + 2 * t + 8];
            split2(v0.x * scale, v0.y * scale, qh[kc][0], ql[kc][0]);
            split2(v1.x * scale, v1.y * scale, qh[kc][1], ql[kc][1]);
            split2(v2.x * scale, v2.y * scale, qh[kc][2], ql[kc][2]);
            split2(v3.x * scale, v3.y * scale, qh[kc][3], ql[kc][3]);
        }
    }

    float O[4][4] = {};
    float m0 = -INFINITY, m1 = -INFINITY, l0 = 0.f, l1 = 0.f;

    for (int ch = 0; ch < 8; ch++) {
        __syncthreads();
        // fill 32-key K/V chunk as split-bf16
        {
            const int key = tid >> 3;
            const int dh4 = (tid & 7) << 2;
            const float* kp_ = &QKV[rowbase + (size_t)(ch * 32 + key) * QKVN + ko + dh4];
            float4 kv = *(const float4*)kp_;
            const int dp = dh4 >> 1;
            uint32_t hh, ll;
            split2(kv.x, kv.y, hh, ll); Ksh[dp * 40 + key] = hh;       Ksl[dp * 40 + key] = ll;
            split2(kv.z, kv.w, hh, ll); Ksh[(dp + 1) * 40 + key] = hh; Ksl[(dp + 1) * 40 + key] = ll;

            const float* vp_ = &QKV[rowbase + (size_t)(ch * 32 + key) * QKVN + vo + dh4];
            float4 vv = *(const float4*)vp_;
            float va[4] = {vv.x, vv.y, vv.z, vv.w};
            const int kp2 = key >> 1, hf = key & 1;
            #pragma unroll
            for (int d = 0; d < 4; d++) {
                __nv_bfloat16 hb = __float2bfloat16_rn(va[d]);
                __nv_bfloat16 lb = __float2bfloat16_rn(va[d] - __bfloat162float(hb));
                ((uint16_t*)&Vsh[kp2 * 40 + dh4 + d])[hf] = __bfloat16_as_ushort(hb);
                ((uint16_t*)&Vsl[kp2 * 40 + dh4 + d])[hf] = __bfloat16_as_ushort(lb);
            }
        }
        __syncthreads();

        // QK^T (split-bf16, 3 terms)
        float Sc[4][4] = {};
        #pragma unroll
        for (int nt = 0; nt < 4; nt++) {
            #pragma unroll
            for (int kc = 0; kc < 2; kc++) {
                uint32_t bh[2], bl[2];
                bh[0] = Ksh[(8 * kc + t) * 40 + 8 * nt + gg];
                bh[1] = Ksh[(8 * kc + t + 4) * 40 + 8 * nt + gg];
                bl[0] = Ksl[(8 * kc + t) * 40 + 8 * nt + gg];
                bl[1] = Ksl[(8 * kc + t + 4) * 40 + 8 * nt + gg];
                mma_bf16(Sc[nt], qh[kc], bh);
                mma_bf16(Sc[nt], qh[kc], bl);
                mma_bf16(Sc[nt], ql[kc], bh);
            }
        }

        // online softmax update
        float mx0 = -INFINITY, mx1 = -INFINITY;
        #pragma unroll
        for (int nt = 0; nt < 4; nt++) {
            const int keyb = ch * 32 + 8 * nt + 2 * t;
            Sc[nt][0] += madd[keyb];
            Sc[nt][1] += madd[keyb + 1];
            Sc[nt][2] += madd[keyb];
            Sc[nt][3] += madd[keyb + 1];
            mx0 = fmaxf(mx0, fmaxf(Sc[nt][0], Sc[nt][1]));
            mx1 = fmaxf(mx1, fmaxf(Sc[nt][2], Sc[nt][3]));
        }
        mx0 = fmaxf(mx0, __shfl_xor_sync(0xffffffffu, mx0, 1));
        mx0 = fmaxf(mx0, __shfl_xor_sync(0xffffffffu, mx0, 2));
        mx1 = fmaxf(mx1, __shfl_xor_sync(0xffffffffu, mx1, 1));
        mx1 = fmaxf(mx1, __shfl_xor_sync(0xffffffffu, mx1, 2));
        const float mn0 = fmaxf(m0, mx0);
        const float mn1 = fmaxf(m1, mx1);
        const float c0 = __expf(m0 - mn0);
        const float c1 = __expf(m1 - mn1);
        float ls0 = 0.f, ls1 = 0.f;
        #pragma unroll
        for (int nt = 0; nt < 4; nt++) {
            float p0 = __expf(Sc[nt][0] - mn0);
            float p1 = __expf(Sc[nt][1] - mn0);
            float p2 = __expf(Sc[nt][2] - mn1);
            float p3 = __expf(Sc[nt][3] - mn1);
            ls0 += p0 + p1;
            ls1 += p2 + p3;
            Sc[nt][0] = p0; Sc[nt][1] = p1; Sc[nt][2] = p2; Sc[nt][3] = p3;
        }
        ls0 += __shfl_xor_sync(0xffffffffu, ls0, 1);
        ls0 += __shfl_xor_sync(0xffffffffu, ls0, 2);
        ls1 += __shfl_xor_sync(0xffffffffu, ls1, 1);
        ls1 += __shfl_xor_sync(0xffffffffu, ls1, 2);
        l0 = l0 * c0 + ls0;
        l1 = l1 * c1 + ls1;
        m0 = mn0;
        m1 = mn1;
        #pragma unroll
        for (int nt = 0; nt < 4; nt++) {
            O[nt][0] *= c0; O[nt][1] *= c0;
            O[nt][2] *= c1; O[nt][3] *= c1;
        }

        // pack P -> bf16 A-fragments
        uint32_t pa_[2][4];
        #pragma unroll
        for (int kc = 0; kc < 2; kc++) {
            pa_[kc][0] = packbf(Sc[2 * kc][0],     Sc[2 * kc][1]);
            pa_[kc][1] = packbf(Sc[2 * kc][2],     Sc[2 * kc][3]);
            pa_[kc][2] = packbf(Sc[2 * kc + 1][0], Sc[2 * kc + 1][1]);
            pa_[kc][3] = packbf(Sc[2 * kc + 1][2], Sc[2 * kc + 1][3]);
        }

        // P @ V (P bf16, V split 2 terms)
        #pragma unroll
        for (int kc = 0; kc < 2; kc++) {
            #pragma unroll
            for (int nt = 0; nt < 4; nt++) {
                uint32_t bh[2], bl[2];
                bh[0] = Vsh[(8 * kc + t) * 40 + 8 * nt + gg];
                bh[1] = Vsh[(8 * kc + t + 4) * 40 + 8 * nt + gg];
                bl[0] = Vsl[(8 * kc + t) * 40 + 8 * nt + gg];
                bl[1] = Vsl[(8 * kc + t + 4) * 40 + 8 * nt + gg];
                mma_bf16(O[nt], pa_[kc], bh);
                mma_bf16(O[nt], pa_[kc], bl);
            }
        }
    }

    // write packed ctx
    const float i0 = 1.0f / l0;
    const float i1 = 1.0f / l1;
    const size_t p0 = (size_t)(b * S + rA) * 128 + h * 16;
    const size_t p1 = (size_t)(b * S + rB) * 128 + h * 16;
    #pragma unroll
    for (int nt = 0; nt < 4; nt++) {
        uint32_t hw, lw;
        split2(O[nt][0] * i0, O[nt][1] * i0, hw, lw);
        cth[p0 + 4 * nt + t] = hw;
        ctl[p0 + 4 * nt + t] = lw;
        split2(O[nt][2] * i1, O[nt][3] * i1, hw, lw);
        cth[p1 + 4 * nt + t] = hw;
        ctl[p1 + 4 * nt + t] = lw;
    }
}

// ---------------- pooling ------------------------------------------------------
__global__ void pool_kernel(const float* __restrict__ x, const float* __restrict__ cmask,
                            const float* __restrict__ pw, const float* __restrict__ pb,
                            float* __restrict__ out)
{
    __shared__ float spw[H];
    __shared__ float sc[S];
    __shared__ float red[8];
    const int b = blockIdx.x, tid = threadIdx.x;
    const int lane = tid & 31, w = tid >> 5;
    spw[tid] = pw[tid];
    __syncthreads();

    for (int row = w; row < S; row += 8) {
        const float* xp = &x[((size_t)b * S + row) * H];
        float4 a0 = *(const float4*)&xp[lane * 4];
        float4 a1 = *(const float4*)&xp[128 + lane * 4];
        float acc = a0.x * spw[lane * 4 + 0] + a0.y * spw[lane * 4 + 1]
                  + a0.z * spw[lane * 4 + 2] + a0.w * spw[lane * 4 + 3]
                  + a1.x * spw[128 + lane * 4 + 0] + a1.y * spw[128 + lane * 4 + 1]
                  + a1.z * spw[128 + lane * 4 + 2] + a1.w * spw[128 + lane * 4 + 3];
        #pragma unroll
        for (int off = 16; off; off >>= 1) acc += __shfl_xor_sync(0xffffffffu, acc, off);
        if (lane == 0)
            sc[row] = acc + pb[0] + (1.f - cmask[b * S + row]) * VERY_NEG;
    }
    __syncthreads();

    float v = sc[tid];
    float mx = v;
    #pragma unroll
    for (int off = 16; off; off >>= 1) mx = fmaxf(mx, __shfl_xor_sync(0xffffffffu, mx, off));
    if (lane == 0) red[w] = mx;
    __syncthreads();
    float bm = red[0];
    #pragma unroll
    for (int i = 1; i < 8; i++) bm = fmaxf(bm, red[i]);
    __syncthreads();
    float e = __expf(v - bm);
    float su = e;
    #pragma unroll
    for (int off = 16; off; off >>= 1) su += __shfl_xor_sync(0xffffffffu, su, off);
    if (lane == 0) red[w] = su;
    __syncthreads();
    float tot = 0.f;
    #pragma unroll
    for (int i = 0; i < 8; i++) tot += red[i];
    sc[tid] = e / tot;
    __syncthreads();

    float acc = 0.f;
    for (int ss = 0; ss < S; ss++)
        acc = fmaf(sc[ss], x[((size_t)b * S + ss) * H + tid], acc);
    out[(size_t)b * H + tid] = acc;
}

// ---------------- host ----------------------------------------------------------
extern "C" void kernel_launch(void* const* d_in, const int* in_sizes, int n_in,
                              void* d_out, int out_size)
{
    const int*   input_ids   = (const int*)d_in[0];
    const float* code_mask   = (const float*)d_in[1];
    const int*   dx_leaves   = (const int*)d_in[2];
    const int*   dx_anc      = (const int*)d_in[3];
    const float* dx_mask     = (const float*)d_in[4];
    const float* embed_init  = (const float*)d_in[5];
    const float* embed_inp   = (const float*)d_in[6];
    const float* attn_w1     = (const float*)d_in[7];
    const float* attn_b1     = (const float*)d_in[8];
    const float* attn_w2     = (const float*)d_in[9];
    const float* attn_b2     = (const float*)d_in[10];
    const float* pool_w      = (const float*)d_in[11];
    const float* pool_b      = (const float*)d_in[12];
    const float* enc_w[2][8];
    for (int z = 0; z < 2; z++)
        for (int j = 0; j < 8; j++)
            enc_w[z][j] = (const float*)d_in[13 + z * 8 + j];
    float* out = (float*)d_out;

    uint32_t *eh, *el, *xvh, *xvl, *xdh, *xdl, *w1h, *w1l;
    uint32_t *cth[2], *ctl[2], *th[2], *tl[2], *fh[2], *fl[2];
    uint32_t *wqkvh[2], *wqkvl[2], *woh[2], *wol[2], *f1h[2], *f1l[2], *f2h[2], *f2l[2];
    float *s, *dag, *xv, *xd, *xdo, *qkv[2], *t[2];
    {
        char* p;
        cudaGetSymbolAddress((void**)&eh, g_eh);   cudaGetSymbolAddress((void**)&el, g_el);
        cudaGetSymbolAddress((void**)&s, g_s);     cudaGetSymbolAddress((void**)&dag, g_dag);
        cudaGetSymbolAddress((void**)&xv, g_xv);   cudaGetSymbolAddress((void**)&xd, g_xd);
        cudaGetSymbolAddress((void**)&xvh, g_xvh); cudaGetSymbolAddress((void**)&xvl, g_xvl);
        cudaGetSymbolAddress((void**)&xdh, g_xdh); cudaGetSymbolAddress((void**)&xdl, g_xdl);
        cudaGetSymbolAddress((void**)&xdo, g_xdo);
        cudaGetSymbolAddress((void**)&w1h, g_w1h); cudaGetSymbolAddress((void**)&w1l, g_w1l);
        cudaGetSymbolAddress((void**)&p, g_qkv);   qkv[0] = (float*)p;    qkv[1] = qkv[0] + (size_t)BS * QKVN;
        cudaGetSymbolAddress((void**)&p, g_t);     t[0] = (float*)p;      t[1] = t[0] + (size_t)BS * H;
        cudaGetSymbolAddress((void**)&p, g_cth);   cth[0] = (uint32_t*)p; cth[1] = cth[0] + (size_t)BS * 128;
        cudaGetSymbolAddress((void**)&p, g_ctl);   ctl[0] = (uint32_t*)p; ctl[1] = ctl[0] + (size_t)BS * 128;
        cudaGetSymbolAddress((void**)&p, g_th);    th[0] = (uint32_t*)p;  th[1] = th[0] + (size_t)BS * 128;
        cudaGetSymbolAddress((void**)&p, g_tl);    tl[0] = (uint32_t*)p;  tl[1] = tl[0] + (size_t)BS * 128;
        cudaGetSymbolAddress((void**)&p, g_fh);    fh[0] = (uint32_t*)p;  fh[1] = fh[0] + (size_t)BS * 512;
        cudaGetSymbolAddress((void**)&p, g_fl);    fl[0] = (uint32_t*)p;  fl[1] = fl[0] + (size_t)BS * 512;
        cudaGetSymbolAddress((void**)&p, g_wqkvh); wqkvh[0] = (uint32_t*)p; wqkvh[1] = wqkvh[0] + 128 * QKVN;
        cudaGetSymbolAddress((void**)&p, g_wqkvl); wqkvl[0] = (uint32_t*)p; wqkvl[1] = wqkvl[0] + 128 * QKVN;
        cudaGetSymbolAddress((void**)&p, g_woh);   woh[0] = (uint32_t*)p;   woh[1] = woh[0] + 128 * 256;
        cudaGetSymbolAddress((void**)&p, g_wol);   wol[0] = (uint32_t*)p;   wol[1] = wol[0] + 128 * 256;
        cudaGetSymbolAddress((void**)&p, g_f1h);   f1h[0] = (uint32_t*)p;   f1h[1] = f1h[0] + 128 * 1024;
        cudaGetSymbolAddress((void**)&p, g_f1l);   f1l[0] = (uint32_t*)p;   f1l[1] = f1l[0] + 128 * 1024;
        cudaGetSymbolAddress((void**)&p, g_f2h);   f2h[0] = (uint32_t*)p;   f2h[1] = f2h[0] + 512 * 256;
        cudaGetSymbolAddress((void**)&p, g_f2l);   f2l[0] = (uint32_t*)p;   f2l[1] = f2l[0] + 512 * 256;
    }

    cudaFuncSetAttribute(tgemm_kernel<true, true, false, true, false, false, true>,
                         cudaFuncAttributeMaxDynamicSharedMemorySize, GSM);
    cudaFuncSetAttribute(tgemm_kernel<false, false, false, false, true, false, false>,
                         cudaFuncAttributeMaxDynamicSharedMemorySize, GSM);
    cudaFuncSetAttribute(tgemm_kernel<false, false, true, false, true, true, false>,
                         cudaFuncAttributeMaxDynamicSharedMemorySize, GSM);
    cudaFuncSetAttribute(tgemm_kernel<true, true, false, false, false, true, false>,
                         cudaFuncAttributeMaxDynamicSharedMemorySize, GSM);
    cudaFuncSetAttribute(tgemm_kernel<false, true, true, false, true, false, false>,
                         cudaFuncAttributeMaxDynamicSharedMemorySize, GSM);

    const int PT = 256;
    pack_contig_kernel<<<(NODES1 * 128 + PT - 1) / PT, PT>>>(embed_init, eh, el, NODES1 * 128);
    s_init_kernel<<<(CA + PT - 1) / PT, PT>>>(s, attn_b2);

    // merged weight packing
    {
        PackAll pa{};
        int cur = 0, si = 0;
        auto add = [&](const float* src, uint32_t* dh, uint32_t* dl,
                       int Khalf, int Nsrc, int Ndst, int coff) {
            pa.seg[si] = {src, dh, dl, Khalf, Nsrc, Ndst, coff, cur};
            cur += Khalf * Nsrc;
            si++;
        };
        add(attn_w1, w1h, w1l, 256, 256, 256, 0);
        for (int z = 0; z < 2; z++) {
            add(enc_w[z][0], wqkvh[z], wqkvl[z], 128, 256, QKVN, 0);
            add(enc_w[z][1], wqkvh[z], wqkvl[z], 128, 256, QKVN, 256);
            add(enc_w[z][2], wqkvh[z], wqkvl[z], 128, 256, QKVN, 512);
            add(enc_w[z][3], woh[z], wol[z], 128, 256, 256, 0);
            add(enc_w[z][4], f1h[z], f1l[z], 128, 1024, 1024, 0);
            add(enc_w[z][6], f2h[z], f2l[z], 512, 256, 256, 0);
        }
        pa.total = cur;
        pack_all_kernel<<<(cur + PT - 1) / PT, PT>>>(pa);
    }

    // DAG MLP: gathered A + fused score
    {
        G2 g{};
        g.Ah0 = g.Ah1 = eh;  g.Al0 = g.Al1 = el;
        g.Bh0 = g.Bh1 = w1h; g.Bl0 = g.Bl1 = w1l;
        g.bias0 = g.bias1 = attn_b1;
        tgemm_kernel<true, true, false, true, false, false, true><<<dim3(2, CA / 128, 1), 256, GSM>>>(
            g, attn_w2, s, CA, 256, 512, dx_leaves, dx_anc);
    }
    dag_softmax_kernel<<<C / 8, 256>>>(s, dx_mask, dx_anc, embed_init, dag);
    embed_gather_kernel<<<(BS * 64 + PT - 1) / PT, PT>>>(input_ids, embed_inp, dag,
                                                         xv, xd, xvh, xvl, xdh, xdl);

    // --- both encoders batched over gridDim.z ---
    {
        G2 g{};
        g.Ah0 = xvh; g.Al0 = xvl; g.Ah1 = xdh; g.Al1 = xdl;
        g.Bh0 = wqkvh[0]; g.Bl0 = wqkvl[0]; g.Bh1 = wqkvh[1]; g.Bl1 = wqkvl[1];
        g.Cm0 = qkv[0]; g.Cm1 = qkv[1];
        tgemm_kernel<false, false, false, false, true, false, false><<<dim3(QKVN / 128, BS / 128, 2), 256, GSM>>>(
            g, nullptr, nullptr, BS, QKVN, H, nullptr, nullptr);
    }
    {
        A2 a{qkv[0], qkv[1], cth[0], ctl[0], cth[1], ctl[1]};
        attention_kernel<<<dim3(NH, Bz, 4), 256>>>(a, code_mask);
    }
    {
        G2 g{};
        g.Ah0 = cth[0]; g.Al0 = ctl[0]; g.Ah1 = cth[1]; g.Al1 = ctl[1];
        g.Bh0 = woh[0]; g.Bl0 = wol[0]; g.Bh1 = woh[1]; g.Bl1 = wol[1];
        g.Res0 = xv; g.Res1 = xd;
        g.Cm0 = t[0]; g.Cm1 = t[1];
        g.Ch0 = th[0]; g.Cl0 = tl[0]; g.Ch1 = th[1]; g.Cl1 = tl[1];
        tgemm_kernel<false, false, true, false, true, true, false><<<dim3(2, BS / 128, 2), 256, GSM>>>(
            g, nullptr, nullptr, BS, H, H, nullptr, nullptr);
    }
    {
        G2 g{};
        g.Ah0 = th[0]; g.Al0 = tl[0]; g.Ah1 = th[1]; g.Al1 = tl[1];
        g.Bh0 = f1h[0]; g.Bl0 = f1l[0]; g.Bh1 = f1h[1]; g.Bl1 = f1l[1];
        g.bias0 = enc_w[0][5]; g.bias1 = enc_w[1][5];
        g.Ch0 = fh[0]; g.Cl0 = fl[0]; g.Ch1 = fh[1]; g.Cl1 = fl[1];
        tgemm_kernel<true, true, false, false, false, true, false><<<dim3(FF / 128, BS / 128, 2), 256, GSM>>>(
            g, nullptr, nullptr, BS, FF, H, nullptr, nullptr);
    }
    {
        G2 g{};
        g.Ah0 = fh[0]; g.Al0 = fl[0]; g.Ah1 = fh[1]; g.Al1 = fl[1];
        g.Bh0 = f2h[0]; g.Bl0 = f2l[0]; g.Bh1 = f2h[1]; g.Bl1 = f2l[1];
        g.bias0 = enc_w[0][7]; g.bias1 = enc_w[1][7];
        g.Res0 = t[0]; g.Res1 = t[1];
        g.Cm0 = out; g.Cm1 = xdo;
        tgemm_kernel<false, true, true, false, true, false, false><<<dim3(2, BS / 128, 2), 256, GSM>>>(
            g, nullptr, nullptr, BS, H, FF, nullptr, nullptr);
    }

    pool_kernel<<<Bz, 256>>>(xdo, code_mask, pool_w, pool_b, out + (size_t)BS * H);
}